// round 1
// baseline (speedup 1.0000x reference)
#include <cuda_runtime.h>
#include <math.h>

// ---------------- problem constants ----------------
#define BB    32
#define HH    56
#define WWI   56
#define LTOK  3136          // 56*56
#define CDIM  512
#define NH    16
#define HDIM  32
#define WSZ   8
#define NTOK  64            // 8*8
#define SHFT  4
#define NWH   7
#define NWIN  49            // 7*7
#define NWTOT 1568          // BB*NWIN
#define MROWS 100352        // BB*LTOK = NWTOT*NTOK
#define HID   2048
#define QKVC  1536

// ---------------- static device scratch (no allocations allowed) ----------------
__device__ float g_xw[(size_t)MROWS * CDIM];      // LN'd windowed input / LN2 output (reused)
__device__ float g_qkv[(size_t)MROWS * QKVC];     // qkv; q-region later reused as attn output
__device__ float g_x1[(size_t)MROWS * CDIM];      // residual after attention
__device__ float g_hidden[(size_t)MROWS * HID];   // MLP hidden
__device__ float g_posbias[NH * NTOK * NTOK];     // 16 x 64 x 64

// ---------------- helpers ----------------
// windowed row p -> flat (b*3136 + r*56 + c) row in original layout
// p = win*64 + t, win = b*49 + wh*7 + ww, t = th*8 + tw
// rolled coord r' = wh*8+th ; source/dest coord r = (r'+SHIFT) % 56
__device__ __forceinline__ size_t win_row_to_flat(int p) {
    int b   = p / LTOK;
    int rem = p - b * LTOK;
    int wl  = rem >> 6;
    int t   = rem & 63;
    int wh  = wl / NWH;
    int ww  = wl - wh * NWH;
    int r   = (wh * WSZ + (t >> 3) + SHFT) % HH;
    int c   = (ww * WSZ + (t & 7)  + SHFT) % WWI;
    return (size_t)b * LTOK + (size_t)r * WWI + c;
}

// ---------------- positional bias table (log-CPB MLP) ----------------
__global__ void posbias_kernel(const float* __restrict__ w1, const float* __restrict__ b1,
                               const float* __restrict__ w2, const float* __restrict__ b2) {
    int n = blockIdx.x;   // 0..63
    int m = threadIdx.x;  // 0..63
    float dh = (float)((n >> 3) - (m >> 3));
    float dw = (float)((n & 7)  - (m & 7));
    float fh = (dh > 0.f) ? log1pf(dh) : ((dh < 0.f) ? -log1pf(-dh) : 0.f);
    float fw = (dw > 0.f) ? log1pf(dw) : ((dw < 0.f) ? -log1pf(-dw) : 0.f);
    float hv[32];
#pragma unroll
    for (int o = 0; o < 32; ++o)
        hv[o] = fmaxf(w1[2 * o] * fh + w1[2 * o + 1] * fw + b1[o], 0.f);
#pragma unroll
    for (int hd = 0; hd < NH; ++hd) {
        float acc = b2[hd];
#pragma unroll
        for (int o = 0; o < 32; ++o) acc += w2[hd * 32 + o] * hv[o];
        g_posbias[hd * (NTOK * NTOK) + n * NTOK + m] = acc;
    }
}

// ---------------- LayerNorm (optionally with shifted-window gather) ----------------
// one block per row (128 threads, float4)
__global__ void ln_kernel(const float* __restrict__ in, const float* __restrict__ gamma,
                          const float* __restrict__ beta, float* __restrict__ out, int gather) {
    int p = blockIdx.x;
    int tid = threadIdx.x;
    size_t srow = gather ? win_row_to_flat(p) : (size_t)p;
    const float4* src = (const float4*)(in + srow * CDIM);
    float4 v = src[tid];
    float s = v.x + v.y + v.z + v.w;
    float q = v.x * v.x + v.y * v.y + v.z * v.z + v.w * v.w;
#pragma unroll
    for (int off = 16; off > 0; off >>= 1) {
        s += __shfl_xor_sync(0xFFFFFFFFu, s, off);
        q += __shfl_xor_sync(0xFFFFFFFFu, q, off);
    }
    __shared__ float sh[8];
    int w = tid >> 5, ln = tid & 31;
    if (ln == 0) { sh[w] = s; sh[4 + w] = q; }
    __syncthreads();
    if (tid < 32) {
        float ss = (ln < 4) ? sh[ln] : 0.f;
        float qq = (ln < 4) ? sh[4 + ln] : 0.f;
#pragma unroll
        for (int off = 2; off > 0; off >>= 1) {
            ss += __shfl_xor_sync(0xFFFFFFFFu, ss, off);
            qq += __shfl_xor_sync(0xFFFFFFFFu, qq, off);
        }
        if (ln == 0) { sh[0] = ss; sh[1] = qq; }
    }
    __syncthreads();
    float mean = sh[0] * (1.f / CDIM);
    float var  = sh[1] * (1.f / CDIM) - mean * mean;
    float rstd = rsqrtf(var + 1e-5f);
    float4 gg = ((const float4*)gamma)[tid];
    float4 bb = ((const float4*)beta)[tid];
    float4 o;
    o.x = (v.x - mean) * rstd * gg.x + bb.x;
    o.y = (v.y - mean) * rstd * gg.y + bb.y;
    o.z = (v.z - mean) * rstd * gg.z + bb.z;
    o.w = (v.w - mean) * rstd * gg.w + bb.w;
    ((float4*)(out + (size_t)p * CDIM))[tid] = o;
}

// ---------------- SGEMM NT: C[M,N] = A[M,K] * B[N,K]^T + bias, templated epilogue ----------------
// MODE 0: C = acc + bias
// MODE 1: proj: scatter windowed row -> flat row, add residual res (original x), write C (=x1)
// MODE 2: C = gelu(acc + bias)    (exact erf)
// MODE 3: C = res + acc + bias    (final output)
#define BM 128
#define BN 128
#define BKK 8

template<int MODE>
__global__ __launch_bounds__(256)
void sgemm_nt(const float* __restrict__ A, int lda,
              const float* __restrict__ B, int ldb,
              const float* __restrict__ bias,
              float* __restrict__ C, int ldc,
              int K,
              const float* __restrict__ res) {
    __shared__ float As[BKK][BM];
    __shared__ float Bs[BKK][BN];

    int tid  = threadIdx.x;
    int arow = tid >> 1;
    int acol = (tid & 1) << 2;
    const float* Ag = A + (size_t)(blockIdx.y * BM + arow) * lda + acol;
    const float* Bg = B + (size_t)(blockIdx.x * BN + arow) * ldb + acol;

    int tx = tid & 15;   // col group
    int ty = tid >> 4;   // row group
    float acc[8][8];
#pragma unroll
    for (int i = 0; i < 8; ++i)
#pragma unroll
        for (int j = 0; j < 8; ++j) acc[i][j] = 0.f;

    int ntiles = K / BKK;
    for (int t = 0; t < ntiles; ++t) {
        float4 av = *(const float4*)(Ag + t * BKK);
        float4 bv = *(const float4*)(Bg + t * BKK);
        __syncthreads();
        As[acol + 0][arow] = av.x; As[acol + 1][arow] = av.y;
        As[acol + 2][arow] = av.z; As[acol + 3][arow] = av.w;
        Bs[acol + 0][arow] = bv.x; Bs[acol + 1][arow] = bv.y;
        Bs[acol + 2][arow] = bv.z; Bs[acol + 3][arow] = bv.w;
        __syncthreads();
#pragma unroll
        for (int k = 0; k < BKK; ++k) {
            float4 a0 = *(const float4*)&As[k][ty * 8];
            float4 a1 = *(const float4*)&As[k][ty * 8 + 4];
            float4 b0 = *(const float4*)&Bs[k][tx * 8];
            float4 b1 = *(const float4*)&Bs[k][tx * 8 + 4];
            float ar[8] = {a0.x, a0.y, a0.z, a0.w, a1.x, a1.y, a1.z, a1.w};
            float br[8] = {b0.x, b0.y, b0.z, b0.w, b1.x, b1.y, b1.z, b1.w};
#pragma unroll
            for (int i = 0; i < 8; ++i)
#pragma unroll
                for (int j = 0; j < 8; ++j) acc[i][j] += ar[i] * br[j];
        }
    }

    int gc0 = blockIdx.x * BN + tx * 8;
    int gr0 = blockIdx.y * BM + ty * 8;
    float4 bs0 = *(const float4*)&bias[gc0];
    float4 bs1 = *(const float4*)&bias[gc0 + 4];
    float bsv[8] = {bs0.x, bs0.y, bs0.z, bs0.w, bs1.x, bs1.y, bs1.z, bs1.w};

#pragma unroll
    for (int i = 0; i < 8; ++i) {
        int gr = gr0 + i;
        size_t crow;
        if (MODE == 1) crow = win_row_to_flat(gr) * (size_t)ldc;
        else           crow = (size_t)gr * ldc;
#pragma unroll
        for (int jj = 0; jj < 8; jj += 4) {
            float v[4];
#pragma unroll
            for (int j = 0; j < 4; ++j) {
                float x = acc[i][jj + j] + bsv[jj + j];
                if (MODE == 2) x = 0.5f * x * (1.0f + erff(x * 0.70710678118654752f));
                v[j] = x;
            }
            if (MODE == 1 || MODE == 3) {
                float4 r = *(const float4*)&res[crow + gc0 + jj];
                v[0] += r.x; v[1] += r.y; v[2] += r.z; v[3] += r.w;
            }
            float4 o = make_float4(v[0], v[1], v[2], v[3]);
            *(float4*)&C[crow + gc0 + jj] = o;
        }
    }
}

// ---------------- windowed attention: one block per (window, head), 64 threads ----------------
__global__ __launch_bounds__(64)
void attn_kernel(float* __restrict__ qkv) {
    __shared__ float sq[NTOK][36];
    __shared__ float sk[NTOK][36];
    __shared__ float sv[NTOK][36];
    __shared__ float sS[NTOK][65];
    __shared__ int   sgb[NTOK];

    int win = blockIdx.x;
    int h   = blockIdx.y;
    int tid = threadIdx.x;
    int wl  = win % NWIN;
    int wh  = wl / NWH;
    int ww  = wl - wh * NWH;

    const float scale = 0.17677669529663687f;   // 1/sqrt(32)

    // cooperative load of q,k,v tiles: 64 rows x 32 cols each
    for (int i = tid; i < NTOK * 8; i += 64) {
        int row = i >> 3;
        int c4  = (i & 7) << 2;
        size_t base = (size_t)(win * NTOK + row) * QKVC + h * HDIM + c4;
        float4 qv = *(const float4*)(qkv + base);
        float4 kv = *(const float4*)(qkv + base + CDIM);
        float4 vv = *(const float4*)(qkv + base + 2 * CDIM);
        sq[row][c4 + 0] = qv.x * scale; sq[row][c4 + 1] = qv.y * scale;
        sq[row][c4 + 2] = qv.z * scale; sq[row][c4 + 3] = qv.w * scale;
        sk[row][c4 + 0] = kv.x; sk[row][c4 + 1] = kv.y;
        sk[row][c4 + 2] = kv.z; sk[row][c4 + 3] = kv.w;
        sv[row][c4 + 0] = vv.x; sv[row][c4 + 1] = vv.y;
        sv[row][c4 + 2] = vv.z; sv[row][c4 + 3] = vv.w;
    }
    // shift-mask group id per token (rolled-frame coordinates)
    {
        int t  = tid;
        int rr = wh * WSZ + (t >> 3);
        int cc = ww * WSZ + (t & 7);
        int gi = (rr < 48) ? 0 : ((rr < 52) ? 1 : 2);
        int gj = (cc < 48) ? 0 : ((cc < 52) ? 1 : 2);
        sgb[t] = gi * 3 + gj;
    }
    __syncthreads();

    int n = tid;
    float qr[HDIM];
#pragma unroll
    for (int d = 0; d < HDIM; ++d) qr[d] = sq[n][d];

    const float* pb = g_posbias + h * (NTOK * NTOK) + n * NTOK;
    int gn = sgb[n];

    float mx = -1e30f;
    for (int m = 0; m < NTOK; ++m) {
        float a = 0.f;
#pragma unroll
        for (int d = 0; d < HDIM; ++d) a += qr[d] * sk[m][d];
        a += pb[m];
        if (gn != sgb[m]) a -= 100.f;
        sS[n][m] = a;
        mx = fmaxf(mx, a);
    }
    float sum = 0.f;
    for (int m = 0; m < NTOK; ++m) {
        float e = expf(sS[n][m] - mx);
        sS[n][m] = e;
        sum += e;
    }
    float inv = 1.f / sum;

    float oacc[HDIM];
#pragma unroll
    for (int d = 0; d < HDIM; ++d) oacc[d] = 0.f;
    for (int m = 0; m < NTOK; ++m) {
        float pw = sS[n][m] * inv;
#pragma unroll
        for (int d = 0; d < HDIM; ++d) oacc[d] += pw * sv[m][d];
    }

    // write attention output into the q-region of qkv (disjoint head columns; safe alias)
    size_t obase = (size_t)(win * NTOK + n) * QKVC + h * HDIM;
#pragma unroll
    for (int d = 0; d < HDIM; d += 4) {
        float4 o = make_float4(oacc[d], oacc[d + 1], oacc[d + 2], oacc[d + 3]);
        *(float4*)(qkv + obase + d) = o;
    }
}

// ---------------- launch ----------------
extern "C" void kernel_launch(void* const* d_in, const int* in_sizes, int n_in,
                              void* d_out, int out_size) {
    const float* x      = (const float*)d_in[0];
    const float* g1     = (const float*)d_in[1];
    const float* be1    = (const float*)d_in[2];
    const float* w_qkv  = (const float*)d_in[3];
    const float* b_qkv  = (const float*)d_in[4];
    const float* pm_w1  = (const float*)d_in[5];
    const float* pm_b1  = (const float*)d_in[6];
    const float* pm_w2  = (const float*)d_in[7];
    const float* pm_b2  = (const float*)d_in[8];
    const float* w_proj = (const float*)d_in[9];
    const float* b_proj = (const float*)d_in[10];
    const float* g2     = (const float*)d_in[11];
    const float* be2    = (const float*)d_in[12];
    const float* w_fc1  = (const float*)d_in[13];
    const float* b_fc1  = (const float*)d_in[14];
    const float* w_fc2  = (const float*)d_in[15];
    const float* b_fc2  = (const float*)d_in[16];
    float* out = (float*)d_out;

    float *p_xw, *p_qkv, *p_x1, *p_hidden;
    cudaGetSymbolAddress((void**)&p_xw, g_xw);
    cudaGetSymbolAddress((void**)&p_qkv, g_qkv);
    cudaGetSymbolAddress((void**)&p_x1, g_x1);
    cudaGetSymbolAddress((void**)&p_hidden, g_hidden);

    // 1. positional bias table
    posbias_kernel<<<NTOK, NTOK>>>(pm_w1, pm_b1, pm_w2, pm_b2);

    // 2. LN1 + shifted-window gather -> g_xw
    ln_kernel<<<MROWS, 128>>>(x, g1, be1, p_xw, 1);

    // 3. QKV GEMM: (100352 x 512) * (1536 x 512)^T -> g_qkv
    sgemm_nt<0><<<dim3(QKVC / BN, MROWS / BM), 256>>>(p_xw, CDIM, w_qkv, CDIM, b_qkv,
                                                      p_qkv, QKVC, CDIM, nullptr);

    // 4. windowed attention (writes into q-region of g_qkv)
    attn_kernel<<<dim3(NWTOT, NH), 64>>>(p_qkv);

    // 5. proj GEMM + window-reverse scatter + residual -> g_x1
    sgemm_nt<1><<<dim3(CDIM / BN, MROWS / BM), 256>>>(p_qkv, QKVC, w_proj, CDIM, b_proj,
                                                      p_x1, CDIM, CDIM, x);

    // 6. LN2 -> g_xw (reuse)
    ln_kernel<<<MROWS, 128>>>(p_x1, g2, be2, p_xw, 0);

    // 7. FC1 + GELU -> g_hidden
    sgemm_nt<2><<<dim3(HID / BN, MROWS / BM), 256>>>(p_xw, CDIM, w_fc1, CDIM, b_fc1,
                                                     p_hidden, HID, CDIM, nullptr);

    // 8. FC2 + residual -> d_out
    sgemm_nt<3><<<dim3(CDIM / BN, MROWS / BM), 256>>>(p_hidden, HID, w_fc2, HID, b_fc2,
                                                      out, CDIM, HID, p_x1);
}

// round 3
// speedup vs baseline: 2.5577x; 2.5577x over previous
#include <cuda_runtime.h>
#include <math.h>
#include <cstdint>

// ---------------- problem constants ----------------
#define BB    32
#define HH    56
#define WWI   56
#define LTOK  3136          // 56*56
#define CDIM  512
#define NH    16
#define HDIM  32
#define WSZ   8
#define NTOK  64            // 8*8
#define SHFT  4
#define NWH   7
#define NWIN  49            // 7*7
#define NWTOT 1568          // BB*NWIN
#define MROWS 100352        // BB*LTOK = NWTOT*NTOK
#define HID   2048
#define QKVC  1536

// ---------------- static device scratch ----------------
__device__ float g_xw[(size_t)MROWS * CDIM];
__device__ float g_qkv[(size_t)MROWS * QKVC];
__device__ float g_x1[(size_t)MROWS * CDIM];
__device__ float g_hidden[(size_t)MROWS * HID];
__device__ float g_posbias[NH * NTOK * NTOK];

// ---------------- helpers ----------------
__device__ __forceinline__ uint32_t smem_u32(const void* p) {
    uint32_t a;
    asm("{ .reg .u64 t; cvta.to.shared.u64 t, %1; cvt.u32.u64 %0, t; }" : "=r"(a) : "l"(p));
    return a;
}
#define CP_ASYNC16(dst, src) \
    asm volatile("cp.async.cg.shared.global [%0], [%1], 16;" :: "r"(dst), "l"(src))
#define CP_COMMIT() asm volatile("cp.async.commit_group;" ::: "memory")
#define CP_WAIT0()  asm volatile("cp.async.wait_group 0;" ::: "memory")
#define CP_WAIT1()  asm volatile("cp.async.wait_group 1;" ::: "memory")

__device__ __forceinline__ void mma_tf32(float* d, const uint32_t* a, uint32_t b0, uint32_t b1) {
    asm volatile(
        "mma.sync.aligned.m16n8k8.row.col.f32.tf32.tf32.f32 "
        "{%0,%1,%2,%3}, {%4,%5,%6,%7}, {%8,%9}, {%0,%1,%2,%3};"
        : "+f"(d[0]), "+f"(d[1]), "+f"(d[2]), "+f"(d[3])
        : "r"(a[0]), "r"(a[1]), "r"(a[2]), "r"(a[3]), "r"(b0), "r"(b1));
}

// windowed row p -> flat row in original (B, H*W) layout
__device__ __forceinline__ size_t win_row_to_flat(int p) {
    int b   = p / LTOK;
    int rem = p - b * LTOK;
    int wl  = rem >> 6;
    int t   = rem & 63;
    int wh  = wl / NWH;
    int ww  = wl - wh * NWH;
    int r   = (wh * WSZ + (t >> 3) + SHFT) % HH;
    int c   = (ww * WSZ + (t & 7)  + SHFT) % WWI;
    return (size_t)b * LTOK + (size_t)r * WWI + c;
}

// ---------------- positional bias table ----------------
__global__ void posbias_kernel(const float* __restrict__ w1, const float* __restrict__ b1,
                               const float* __restrict__ w2, const float* __restrict__ b2) {
    int n = blockIdx.x;
    int m = threadIdx.x;
    float dh = (float)((n >> 3) - (m >> 3));
    float dw = (float)((n & 7)  - (m & 7));
    float fh = (dh > 0.f) ? log1pf(dh) : ((dh < 0.f) ? -log1pf(-dh) : 0.f);
    float fw = (dw > 0.f) ? log1pf(dw) : ((dw < 0.f) ? -log1pf(-dw) : 0.f);
    float hv[32];
#pragma unroll
    for (int o = 0; o < 32; ++o)
        hv[o] = fmaxf(w1[2 * o] * fh + w1[2 * o + 1] * fw + b1[o], 0.f);
#pragma unroll
    for (int hd = 0; hd < NH; ++hd) {
        float acc = b2[hd];
#pragma unroll
        for (int o = 0; o < 32; ++o) acc += w2[hd * 32 + o] * hv[o];
        g_posbias[hd * (NTOK * NTOK) + n * NTOK + m] = acc;
    }
}

// ---------------- LayerNorm (+ optional shifted-window gather) ----------------
__global__ void ln_kernel(const float* __restrict__ in, const float* __restrict__ gamma,
                          const float* __restrict__ beta, float* __restrict__ out, int gather) {
    int p = blockIdx.x;
    int tid = threadIdx.x;
    size_t srow = gather ? win_row_to_flat(p) : (size_t)p;
    const float4* src = (const float4*)(in + srow * CDIM);
    float4 v = src[tid];
    float s = v.x + v.y + v.z + v.w;
    float q = v.x * v.x + v.y * v.y + v.z * v.z + v.w * v.w;
#pragma unroll
    for (int off = 16; off > 0; off >>= 1) {
        s += __shfl_xor_sync(0xFFFFFFFFu, s, off);
        q += __shfl_xor_sync(0xFFFFFFFFu, q, off);
    }
    __shared__ float sh[8];
    int w = tid >> 5, ln = tid & 31;
    if (ln == 0) { sh[w] = s; sh[4 + w] = q; }
    __syncthreads();
    if (tid < 32) {
        float ss = (ln < 4) ? sh[ln] : 0.f;
        float qq = (ln < 4) ? sh[4 + ln] : 0.f;
#pragma unroll
        for (int off = 2; off > 0; off >>= 1) {
            ss += __shfl_xor_sync(0xFFFFFFFFu, ss, off);
            qq += __shfl_xor_sync(0xFFFFFFFFu, qq, off);
        }
        if (ln == 0) { sh[0] = ss; sh[1] = qq; }
    }
    __syncthreads();
    float mean = sh[0] * (1.f / CDIM);
    float var  = sh[1] * (1.f / CDIM) - mean * mean;
    float rstd = rsqrtf(var + 1e-5f);
    float4 gg = ((const float4*)gamma)[tid];
    float4 bb = ((const float4*)beta)[tid];
    float4 o;
    o.x = (v.x - mean) * rstd * gg.x + bb.x;
    o.y = (v.y - mean) * rstd * gg.y + bb.y;
    o.z = (v.z - mean) * rstd * gg.z + bb.z;
    o.w = (v.w - mean) * rstd * gg.w + bb.w;
    ((float4*)(out + (size_t)p * CDIM))[tid] = o;
}

// ---------------- tf32 mma.sync GEMM NT: C[M,N] = A[M,K]*B[N,K]^T + epilogue ----------------
// 128x128x16 CTA tile, 256 threads (8 warps, 4m x 2n), warp tile 32x64 (2x8 m16n8k8).
// MODE 0: C = acc + bias
// MODE 1: scatter windowed row -> flat row, + residual res
// MODE 2: C = gelu(acc + bias)
// MODE 3: C = res + acc + bias
#define BK 16
#define SSTR 20   // smem row stride in floats (padded)

template<int MODE>
__global__ __launch_bounds__(256, 2)
void tgemm(const float* __restrict__ A, int lda,
           const float* __restrict__ B, int ldb,
           const float* __restrict__ bias,
           float* __restrict__ C, int ldc, int K,
           const float* __restrict__ res) {
    __shared__ float As[2][128][SSTR];
    __shared__ float Bs[2][128][SSTR];

    int tid = threadIdx.x;
    int wid = tid >> 5, lane = tid & 31;
    int g   = lane >> 2;          // groupID 0..7
    int tig = lane & 3;           // thread-in-group 0..3
    int warp_row = wid >> 1;      // 0..3 -> 32 rows each
    int warp_col = wid & 1;       // 0..1 -> 64 cols each

    const float* Ag = A + (size_t)(blockIdx.y * 128) * lda;
    const float* Bg = B + (size_t)(blockIdx.x * 128) * ldb;

    // global->smem task mapping: 512 tasks of 16B per tile, 2 per thread
    int r0 = (tid * 2) >> 2;          // task = tid*2 + i
    int c0 = (tid * 2) & 3;

    float acc[2][8][4];
#pragma unroll
    for (int mt = 0; mt < 2; ++mt)
#pragma unroll
        for (int nt = 0; nt < 8; ++nt)
#pragma unroll
            for (int j = 0; j < 4; ++j) acc[mt][nt][j] = 0.f;

    int ntiles = K / BK;

    // prologue: load tile 0 into buffer 0
    {
        int k0 = 0;
#pragma unroll
        for (int i = 0; i < 2; ++i) {
            int task = tid * 2 + i;
            int r = task >> 2, cg = task & 3;
            CP_ASYNC16(smem_u32(&As[0][r][cg * 4]), Ag + (size_t)r * lda + k0 + cg * 4);
            CP_ASYNC16(smem_u32(&Bs[0][r][cg * 4]), Bg + (size_t)r * ldb + k0 + cg * 4);
        }
        CP_COMMIT();
    }

    for (int t = 0; t < ntiles; ++t) {
        int buf = t & 1;
        if (t + 1 < ntiles) {
            int k0 = (t + 1) * BK;
            int nb = buf ^ 1;
#pragma unroll
            for (int i = 0; i < 2; ++i) {
                int task = tid * 2 + i;
                int r = task >> 2, cg = task & 3;
                CP_ASYNC16(smem_u32(&As[nb][r][cg * 4]), Ag + (size_t)r * lda + k0 + cg * 4);
                CP_ASYNC16(smem_u32(&Bs[nb][r][cg * 4]), Bg + (size_t)r * ldb + k0 + cg * 4);
            }
            CP_COMMIT();
            CP_WAIT1();
        } else {
            CP_WAIT0();
        }
        __syncthreads();

#pragma unroll
        for (int ks = 0; ks < 2; ++ks) {
            int kk = ks * 8;
            uint32_t af[2][4];
#pragma unroll
            for (int mt = 0; mt < 2; ++mt) {
                int rb = warp_row * 32 + mt * 16;
                af[mt][0] = __float_as_uint(As[buf][rb + g][kk + tig]);
                af[mt][1] = __float_as_uint(As[buf][rb + g + 8][kk + tig]);
                af[mt][2] = __float_as_uint(As[buf][rb + g][kk + tig + 4]);
                af[mt][3] = __float_as_uint(As[buf][rb + g + 8][kk + tig + 4]);
            }
#pragma unroll
            for (int nt = 0; nt < 8; ++nt) {
                int nb = warp_col * 64 + nt * 8;
                uint32_t b0 = __float_as_uint(Bs[buf][nb + g][kk + tig]);
                uint32_t b1 = __float_as_uint(Bs[buf][nb + g][kk + tig + 4]);
                mma_tf32(acc[0][nt], af[0], b0, b1);
                mma_tf32(acc[1][nt], af[1], b0, b1);
            }
        }
        __syncthreads();
    }

    // ---------------- epilogue ----------------
    int gr_base = blockIdx.y * 128 + warp_row * 32;
    int gc_base = blockIdx.x * 128 + warp_col * 64;

    // 4 distinct output rows per thread: (mt, half)
    size_t crow[2][2];
#pragma unroll
    for (int mt = 0; mt < 2; ++mt) {
#pragma unroll
        for (int hf = 0; hf < 2; ++hf) {
            int gr = gr_base + mt * 16 + g + hf * 8;
            crow[mt][hf] = (MODE == 1) ? win_row_to_flat(gr) * (size_t)ldc
                                       : (size_t)gr * ldc;
        }
    }

#pragma unroll
    for (int nt = 0; nt < 8; ++nt) {
        int col = gc_base + nt * 8 + tig * 2;
        float2 bs = *(const float2*)&bias[col];
#pragma unroll
        for (int mt = 0; mt < 2; ++mt) {
#pragma unroll
            for (int hf = 0; hf < 2; ++hf) {
                float v0 = acc[mt][nt][hf * 2 + 0] + bs.x;
                float v1 = acc[mt][nt][hf * 2 + 1] + bs.y;
                if (MODE == 2) {
                    v0 = 0.5f * v0 * (1.0f + erff(v0 * 0.70710678118654752f));
                    v1 = 0.5f * v1 * (1.0f + erff(v1 * 0.70710678118654752f));
                }
                if (MODE == 1 || MODE == 3) {
                    float2 rr = *(const float2*)&res[crow[mt][hf] + col];
                    v0 += rr.x; v1 += rr.y;
                }
                *(float2*)&C[crow[mt][hf] + col] = make_float2(v0, v1);
            }
        }
    }
}

// ---------------- windowed attention: one block per (window, head), 64 threads ----------------
__global__ __launch_bounds__(64)
void attn_kernel(float* __restrict__ qkv) {
    __shared__ float sq[NTOK][36];
    __shared__ float sk[NTOK][36];
    __shared__ float sv[NTOK][36];
    __shared__ float sS[NTOK][65];
    __shared__ int   sgb[NTOK];

    int win = blockIdx.x;
    int h   = blockIdx.y;
    int tid = threadIdx.x;
    int wl  = win % NWIN;
    int wh  = wl / NWH;
    int ww  = wl - wh * NWH;

    const float scale = 0.17677669529663687f;

    for (int i = tid; i < NTOK * 8; i += 64) {
        int row = i >> 3;
        int c4  = (i & 7) << 2;
        size_t base = (size_t)(win * NTOK + row) * QKVC + h * HDIM + c4;
        float4 qv = *(const float4*)(qkv + base);
        float4 kv = *(const float4*)(qkv + base + CDIM);
        float4 vv = *(const float4*)(qkv + base + 2 * CDIM);
        sq[row][c4 + 0] = qv.x * scale; sq[row][c4 + 1] = qv.y * scale;
        sq[row][c4 + 2] = qv.z * scale; sq[row][c4 + 3] = qv.w * scale;
        sk[row][c4 + 0] = kv.x; sk[row][c4 + 1] = kv.y;
        sk[row][c4 + 2] = kv.z; sk[row][c4 + 3] = kv.w;
        sv[row][c4 + 0] = vv.x; sv[row][c4 + 1] = vv.y;
        sv[row][c4 + 2] = vv.z; sv[row][c4 + 3] = vv.w;
    }
    {
        int t  = tid;
        int rr = wh * WSZ + (t >> 3);
        int cc = ww * WSZ + (t & 7);
        int gi = (rr < 48) ? 0 : ((rr < 52) ? 1 : 2);
        int gj = (cc < 48) ? 0 : ((cc < 52) ? 1 : 2);
        sgb[t] = gi * 3 + gj;
    }
    __syncthreads();

    int n = tid;
    float qr[HDIM];
#pragma unroll
    for (int d = 0; d < HDIM; ++d) qr[d] = sq[n][d];

    const float* pb = g_posbias + h * (NTOK * NTOK) + n * NTOK;
    int gn = sgb[n];

    float mx = -1e30f;
    for (int m = 0; m < NTOK; ++m) {
        float a = 0.f;
#pragma unroll
        for (int d = 0; d < HDIM; ++d) a += qr[d] * sk[m][d];
        a += pb[m];
        if (gn != sgb[m]) a -= 100.f;
        sS[n][m] = a;
        mx = fmaxf(mx, a);
    }
    float sum = 0.f;
    for (int m = 0; m < NTOK; ++m) {
        float e = expf(sS[n][m] - mx);
        sS[n][m] = e;
        sum += e;
    }
    float inv = 1.f / sum;

    float oacc[HDIM];
#pragma unroll
    for (int d = 0; d < HDIM; ++d) oacc[d] = 0.f;
    for (int m = 0; m < NTOK; ++m) {
        float pw = sS[n][m] * inv;
#pragma unroll
        for (int d = 0; d < HDIM; ++d) oacc[d] += pw * sv[m][d];
    }

    size_t obase = (size_t)(win * NTOK + n) * QKVC + h * HDIM;
#pragma unroll
    for (int d = 0; d < HDIM; d += 4) {
        *(float4*)(qkv + obase + d) = make_float4(oacc[d], oacc[d + 1], oacc[d + 2], oacc[d + 3]);
    }
}

// ---------------- launch ----------------
extern "C" void kernel_launch(void* const* d_in, const int* in_sizes, int n_in,
                              void* d_out, int out_size) {
    const float* x      = (const float*)d_in[0];
    const float* g1     = (const float*)d_in[1];
    const float* be1    = (const float*)d_in[2];
    const float* w_qkv  = (const float*)d_in[3];
    const float* b_qkv  = (const float*)d_in[4];
    const float* pm_w1  = (const float*)d_in[5];
    const float* pm_b1  = (const float*)d_in[6];
    const float* pm_w2  = (const float*)d_in[7];
    const float* pm_b2  = (const float*)d_in[8];
    const float* w_proj = (const float*)d_in[9];
    const float* b_proj = (const float*)d_in[10];
    const float* g2     = (const float*)d_in[11];
    const float* be2    = (const float*)d_in[12];
    const float* w_fc1  = (const float*)d_in[13];
    const float* b_fc1  = (const float*)d_in[14];
    const float* w_fc2  = (const float*)d_in[15];
    const float* b_fc2  = (const float*)d_in[16];
    float* out = (float*)d_out;

    float *p_xw, *p_qkv, *p_x1, *p_hidden;
    cudaGetSymbolAddress((void**)&p_xw, g_xw);
    cudaGetSymbolAddress((void**)&p_qkv, g_qkv);
    cudaGetSymbolAddress((void**)&p_x1, g_x1);
    cudaGetSymbolAddress((void**)&p_hidden, g_hidden);

    // 1. positional bias table
    posbias_kernel<<<NTOK, NTOK>>>(pm_w1, pm_b1, pm_w2, pm_b2);

    // 2. LN1 + shifted-window gather -> g_xw
    ln_kernel<<<MROWS, 128>>>(x, g1, be1, p_xw, 1);

    // 3. QKV GEMM (tf32 mma.sync tensor cores)
    tgemm<0><<<dim3(QKVC / 128, MROWS / 128), 256>>>(
        p_xw, CDIM, w_qkv, CDIM, b_qkv, p_qkv, QKVC, CDIM, nullptr);

    // 4. windowed attention (writes into q-region of g_qkv)
    attn_kernel<<<dim3(NWTOT, NH), 64>>>(p_qkv);

    // 5. proj GEMM + window-reverse scatter + residual -> g_x1
    tgemm<1><<<dim3(CDIM / 128, MROWS / 128), 256>>>(
        p_qkv, QKVC, w_proj, CDIM, b_proj, p_x1, CDIM, CDIM, x);

    // 6. LN2 -> g_xw
    ln_kernel<<<MROWS, 128>>>(p_x1, g2, be2, p_xw, 0);

    // 7. FC1 + GELU -> g_hidden
    tgemm<2><<<dim3(HID / 128, MROWS / 128), 256>>>(
        p_xw, CDIM, w_fc1, CDIM, b_fc1, p_hidden, HID, CDIM, nullptr);

    // 8. FC2 + residual -> d_out
    tgemm<3><<<dim3(CDIM / 128, MROWS / 128), 256>>>(
        p_hidden, HID, w_fc2, HID, b_fc2, out, CDIM, HID, p_x1);
}

// round 4
// speedup vs baseline: 3.0862x; 1.2067x over previous
#include <cuda_runtime.h>
#include <math.h>
#include <cstdint>

// ---------------- problem constants ----------------
#define BB    32
#define HH    56
#define WWI   56
#define LTOK  3136          // 56*56
#define CDIM  512
#define NH    16
#define HDIM  32
#define WSZ   8
#define NTOK  64            // 8*8
#define SHFT  4
#define NWH   7
#define NWIN  49            // 7*7
#define NWTOT 1568          // BB*NWIN
#define MROWS 100352        // BB*LTOK = NWTOT*NTOK
#define HID   2048
#define QKVC  1536

// ---------------- static device scratch ----------------
__device__ float g_xw[(size_t)MROWS * CDIM];
__device__ float g_qkv[(size_t)MROWS * QKVC];
__device__ float g_x1[(size_t)MROWS * CDIM];
__device__ float g_hidden[(size_t)MROWS * HID];
__device__ float g_posbias[NH * NTOK * NTOK];

// ---------------- helpers ----------------
__device__ __forceinline__ uint32_t smem_u32(const void* p) {
    uint32_t a;
    asm("{ .reg .u64 t; cvta.to.shared.u64 t, %1; cvt.u32.u64 %0, t; }" : "=r"(a) : "l"(p));
    return a;
}
#define CP_ASYNC16(dst, src) \
    asm volatile("cp.async.cg.shared.global [%0], [%1], 16;" :: "r"(dst), "l"(src))
#define CP_COMMIT() asm volatile("cp.async.commit_group;" ::: "memory")
#define CP_WAIT(n)  asm volatile("cp.async.wait_group %0;" :: "n"(n) : "memory")

#define LDSM4(r, addr) \
    asm volatile("ldmatrix.sync.aligned.m8n8.x4.shared.b16 {%0,%1,%2,%3}, [%4];" \
        : "=r"((r)[0]), "=r"((r)[1]), "=r"((r)[2]), "=r"((r)[3]) : "r"(addr))

__device__ __forceinline__ void mma_tf32(float* d, const uint32_t* a, uint32_t b0, uint32_t b1) {
    asm volatile(
        "mma.sync.aligned.m16n8k8.row.col.f32.tf32.tf32.f32 "
        "{%0,%1,%2,%3}, {%4,%5,%6,%7}, {%8,%9}, {%0,%1,%2,%3};"
        : "+f"(d[0]), "+f"(d[1]), "+f"(d[2]), "+f"(d[3])
        : "r"(a[0]), "r"(a[1]), "r"(a[2]), "r"(a[3]), "r"(b0), "r"(b1));
}

// windowed row p -> flat row in original (B, H*W) layout
__device__ __forceinline__ size_t win_row_to_flat(int p) {
    int b   = p / LTOK;
    int rem = p - b * LTOK;
    int wl  = rem >> 6;
    int t   = rem & 63;
    int wh  = wl / NWH;
    int ww  = wl - wh * NWH;
    int r   = (wh * WSZ + (t >> 3) + SHFT) % HH;
    int c   = (ww * WSZ + (t & 7)  + SHFT) % WWI;
    return (size_t)b * LTOK + (size_t)r * WWI + c;
}

// ---------------- positional bias table ----------------
__global__ void posbias_kernel(const float* __restrict__ w1, const float* __restrict__ b1,
                               const float* __restrict__ w2, const float* __restrict__ b2) {
    int n = blockIdx.x;
    int m = threadIdx.x;
    float dh = (float)((n >> 3) - (m >> 3));
    float dw = (float)((n & 7)  - (m & 7));
    float fh = (dh > 0.f) ? log1pf(dh) : ((dh < 0.f) ? -log1pf(-dh) : 0.f);
    float fw = (dw > 0.f) ? log1pf(dw) : ((dw < 0.f) ? -log1pf(-dw) : 0.f);
    float hv[32];
#pragma unroll
    for (int o = 0; o < 32; ++o)
        hv[o] = fmaxf(w1[2 * o] * fh + w1[2 * o + 1] * fw + b1[o], 0.f);
#pragma unroll
    for (int hd = 0; hd < NH; ++hd) {
        float acc = b2[hd];
#pragma unroll
        for (int o = 0; o < 32; ++o) acc += w2[hd * 32 + o] * hv[o];
        g_posbias[hd * (NTOK * NTOK) + n * NTOK + m] = acc;
    }
}

// ---------------- LayerNorm: warp-per-row, 8 rows per 256-thread block ----------------
__global__ __launch_bounds__(256)
void ln_kernel(const float* __restrict__ in, const float* __restrict__ gamma,
               const float* __restrict__ beta, float* __restrict__ out, int gather) {
    int warp = threadIdx.x >> 5, lane = threadIdx.x & 31;
    int p = blockIdx.x * 8 + warp;
    size_t srow = gather ? win_row_to_flat(p) : (size_t)p;
    const float4* src = (const float4*)(in + srow * CDIM);
    float4 v[4];
#pragma unroll
    for (int i = 0; i < 4; ++i) v[i] = src[lane + 32 * i];
    float s = 0.f, q = 0.f;
#pragma unroll
    for (int i = 0; i < 4; ++i) {
        s += v[i].x + v[i].y + v[i].z + v[i].w;
        q += v[i].x * v[i].x + v[i].y * v[i].y + v[i].z * v[i].z + v[i].w * v[i].w;
    }
#pragma unroll
    for (int off = 16; off > 0; off >>= 1) {
        s += __shfl_xor_sync(0xFFFFFFFFu, s, off);
        q += __shfl_xor_sync(0xFFFFFFFFu, q, off);
    }
    float mean = s * (1.f / CDIM);
    float var  = q * (1.f / CDIM) - mean * mean;
    float rstd = rsqrtf(var + 1e-5f);
    float4* dst = (float4*)(out + (size_t)p * CDIM);
#pragma unroll
    for (int i = 0; i < 4; ++i) {
        float4 gg = ((const float4*)gamma)[lane + 32 * i];
        float4 bb = ((const float4*)beta)[lane + 32 * i];
        float4 o;
        o.x = (v[i].x - mean) * rstd * gg.x + bb.x;
        o.y = (v[i].y - mean) * rstd * gg.y + bb.y;
        o.z = (v[i].z - mean) * rstd * gg.z + bb.z;
        o.w = (v[i].w - mean) * rstd * gg.w + bb.w;
        dst[lane + 32 * i] = o;
    }
}

// ---------------- tf32 mma.sync GEMM NT, ldmatrix + 3-stage cp.async ----------------
// 128x128x16 CTA tile, 256 threads (8 warps, 4m x 2n), warp tile 32x64.
// MODE 0: C = acc + bias ; MODE 1: window-reverse scatter + residual
// MODE 2: gelu(acc+bias) ; MODE 3: res + acc + bias
#define BK 16
#define SSTR 20                      // smem row stride (floats)
#define STAGE_F (2 * 128 * SSTR)     // floats per stage (A tile + B tile)
#define NSTAGE 3
#define TG_SMEM (NSTAGE * STAGE_F * 4)

template<int MODE>
__global__ __launch_bounds__(256, 2)
void tgemm(const float* __restrict__ A, int lda,
           const float* __restrict__ B, int ldb,
           const float* __restrict__ bias,
           float* __restrict__ C, int ldc, int K,
           const float* __restrict__ res) {
    extern __shared__ float smf[];
    uint32_t sb = smem_u32(smf);

    int tid = threadIdx.x;
    int wid = tid >> 5, lane = tid & 31;
    int g   = lane >> 2;
    int tig = lane & 3;
    int warp_row = wid >> 1;
    int warp_col = wid & 1;

    const float* Ag = A + (size_t)(blockIdx.y * 128) * lda;
    const float* Bg = B + (size_t)(blockIdx.x * 128) * ldb;

    // cp.async task mapping: 2 tasks/thread per tile (512 x 16B)
    int r_t[2], cg_t[2];
#pragma unroll
    for (int i = 0; i < 2; ++i) {
        int task = tid * 2 + i;
        r_t[i]  = task >> 2;
        cg_t[i] = (task & 3) * 4;
    }

    // ldmatrix per-thread offsets (floats, within stage)
    // A: matrices {rows rb..+7 col kk | rows rb+8..15 col kk | rows rb..+7 col kk+4 | rows +8 col kk+4}
    uint32_t aoff[2];
#pragma unroll
    for (int mt = 0; mt < 2; ++mt)
        aoff[mt] = (uint32_t)((warp_row * 32 + mt * 16 + (lane & 15)) * SSTR + (lane >> 4) * 4);
    // B: pair p covers nt=2p (b0,b1) and nt=2p+1 (b0,b1)
    uint32_t boff[4];
    {
        int row_b = (lane & 7) + ((lane >> 4) << 3);
        int col_b = ((lane >> 3) & 1) * 4;
#pragma unroll
        for (int p = 0; p < 4; ++p)
            boff[p] = (uint32_t)(128 * SSTR + (warp_col * 64 + p * 16 + row_b) * SSTR + col_b);
    }

    float acc[2][8][4];
#pragma unroll
    for (int mt = 0; mt < 2; ++mt)
#pragma unroll
        for (int nt = 0; nt < 8; ++nt)
#pragma unroll
            for (int j = 0; j < 4; ++j) acc[mt][nt][j] = 0.f;

    int ntiles = K / BK;

    // prologue: tiles 0,1 into stages 0,1
#pragma unroll
    for (int s = 0; s < 2; ++s) {
        int k0 = s * BK;
        uint32_t st = sb + s * (STAGE_F * 4);
#pragma unroll
        for (int i = 0; i < 2; ++i) {
            CP_ASYNC16(st + (r_t[i] * SSTR + cg_t[i]) * 4, Ag + (size_t)r_t[i] * lda + k0 + cg_t[i]);
            CP_ASYNC16(st + (128 * SSTR + r_t[i] * SSTR + cg_t[i]) * 4, Bg + (size_t)r_t[i] * ldb + k0 + cg_t[i]);
        }
        CP_COMMIT();
    }

    int stage = 0;       // stage of tile t
    for (int t = 0; t < ntiles; ++t) {
        CP_WAIT(1);
        __syncthreads();
        // prefetch tile t+2 into stage (stage+2)%3
        if (t + 2 < ntiles) {
            int k0 = (t + 2) * BK;
            int s2 = stage + 2; if (s2 >= NSTAGE) s2 -= NSTAGE;
            uint32_t st = sb + s2 * (STAGE_F * 4);
#pragma unroll
            for (int i = 0; i < 2; ++i) {
                CP_ASYNC16(st + (r_t[i] * SSTR + cg_t[i]) * 4, Ag + (size_t)r_t[i] * lda + k0 + cg_t[i]);
                CP_ASYNC16(st + (128 * SSTR + r_t[i] * SSTR + cg_t[i]) * 4, Bg + (size_t)r_t[i] * ldb + k0 + cg_t[i]);
            }
        }
        CP_COMMIT();

        uint32_t sbase = sb + stage * (STAGE_F * 4);
#pragma unroll
        for (int ks = 0; ks < 2; ++ks) {
            uint32_t kb = ks * 32;   // 8 floats
            uint32_t af[2][4], bf[4][4];
#pragma unroll
            for (int mt = 0; mt < 2; ++mt) LDSM4(af[mt], sbase + aoff[mt] * 4 + kb);
#pragma unroll
            for (int p = 0; p < 4; ++p)    LDSM4(bf[p], sbase + boff[p] * 4 + kb);
#pragma unroll
            for (int p = 0; p < 4; ++p) {
                mma_tf32(acc[0][2 * p + 0], af[0], bf[p][0], bf[p][1]);
                mma_tf32(acc[1][2 * p + 0], af[1], bf[p][0], bf[p][1]);
                mma_tf32(acc[0][2 * p + 1], af[0], bf[p][2], bf[p][3]);
                mma_tf32(acc[1][2 * p + 1], af[1], bf[p][2], bf[p][3]);
            }
        }
        if (++stage >= NSTAGE) stage -= NSTAGE;
    }

    // ---------------- epilogue ----------------
    int gr_base = blockIdx.y * 128 + warp_row * 32;
    int gc_base = blockIdx.x * 128 + warp_col * 64;

    size_t crow[2][2];
#pragma unroll
    for (int mt = 0; mt < 2; ++mt)
#pragma unroll
        for (int hf = 0; hf < 2; ++hf) {
            int gr = gr_base + mt * 16 + g + hf * 8;
            crow[mt][hf] = (MODE == 1) ? win_row_to_flat(gr) * (size_t)ldc : (size_t)gr * ldc;
        }

#pragma unroll
    for (int nt = 0; nt < 8; ++nt) {
        int col = gc_base + nt * 8 + tig * 2;
        float2 bs = *(const float2*)&bias[col];
#pragma unroll
        for (int mt = 0; mt < 2; ++mt)
#pragma unroll
            for (int hf = 0; hf < 2; ++hf) {
                float v0 = acc[mt][nt][hf * 2 + 0] + bs.x;
                float v1 = acc[mt][nt][hf * 2 + 1] + bs.y;
                if (MODE == 2) {
                    v0 = 0.5f * v0 * (1.0f + erff(v0 * 0.70710678118654752f));
                    v1 = 0.5f * v1 * (1.0f + erff(v1 * 0.70710678118654752f));
                }
                if (MODE == 1 || MODE == 3) {
                    float2 rr = *(const float2*)&res[crow[mt][hf] + col];
                    v0 += rr.x; v1 += rr.y;
                }
                *(float2*)&C[crow[mt][hf] + col] = make_float2(v0, v1);
            }
    }
}

// ---------------- windowed attention: one block per (window, head), 64 threads ----------------
__global__ __launch_bounds__(64)
void attn_kernel(float* __restrict__ qkv) {
    __shared__ float sq[NTOK][36];
    __shared__ float sk[NTOK][36];
    __shared__ float sv[NTOK][36];
    __shared__ float sS[NTOK][68];
    __shared__ int   sgb[NTOK];

    int win = blockIdx.x;
    int h   = blockIdx.y;
    int tid = threadIdx.x;
    int wl  = win % NWIN;
    int wh  = wl / NWH;
    int ww  = wl - wh * NWH;

    const float scale = 0.17677669529663687f;

    for (int i = tid; i < NTOK * 8; i += 64) {
        int row = i >> 3;
        int c4  = (i & 7) << 2;
        size_t base = (size_t)(win * NTOK + row) * QKVC + h * HDIM + c4;
        float4 qv = *(const float4*)(qkv + base);
        float4 kv = *(const float4*)(qkv + base + CDIM);
        float4 vv = *(const float4*)(qkv + base + 2 * CDIM);
        sq[row][c4 + 0] = qv.x * scale; sq[row][c4 + 1] = qv.y * scale;
        sq[row][c4 + 2] = qv.z * scale; sq[row][c4 + 3] = qv.w * scale;
        sk[row][c4 + 0] = kv.x; sk[row][c4 + 1] = kv.y;
        sk[row][c4 + 2] = kv.z; sk[row][c4 + 3] = kv.w;
        sv[row][c4 + 0] = vv.x; sv[row][c4 + 1] = vv.y;
        sv[row][c4 + 2] = vv.z; sv[row][c4 + 3] = vv.w;
    }
    {
        int t  = tid;
        int rr = wh * WSZ + (t >> 3);
        int cc = ww * WSZ + (t & 7);
        int gi = (rr < 48) ? 0 : ((rr < 52) ? 1 : 2);
        int gj = (cc < 48) ? 0 : ((cc < 52) ? 1 : 2);
        sgb[t] = gi * 3 + gj;
    }
    __syncthreads();

    int n = tid;
    float qr[HDIM];
#pragma unroll
    for (int d = 0; d < HDIM; d += 4) {
        float4 t4 = *(const float4*)&sq[n][d];
        qr[d] = t4.x; qr[d + 1] = t4.y; qr[d + 2] = t4.z; qr[d + 3] = t4.w;
    }

    const float* pb = g_posbias + h * (NTOK * NTOK) + n * NTOK;
    int gn = sgb[n];

    float mx = -1e30f;
#pragma unroll 2
    for (int m0 = 0; m0 < NTOK; m0 += 4) {
        float4 pbv = *(const float4*)&pb[m0];
        float a[4] = {pbv.x, pbv.y, pbv.z, pbv.w};
#pragma unroll
        for (int j = 0; j < 4; ++j) {
            int m = m0 + j;
            float s = 0.f;
#pragma unroll
            for (int d = 0; d < HDIM; d += 4) {
                float4 kv = *(const float4*)&sk[m][d];
                s += qr[d] * kv.x + qr[d + 1] * kv.y + qr[d + 2] * kv.z + qr[d + 3] * kv.w;
            }
            a[j] += s;
            if (gn != sgb[m]) a[j] -= 100.f;
            mx = fmaxf(mx, a[j]);
        }
        *(float4*)&sS[n][m0] = make_float4(a[0], a[1], a[2], a[3]);
    }

    float sum = 0.f;
#pragma unroll
    for (int m0 = 0; m0 < NTOK; m0 += 4) {
        float4 e = *(float4*)&sS[n][m0];
        e.x = expf(e.x - mx); e.y = expf(e.y - mx);
        e.z = expf(e.z - mx); e.w = expf(e.w - mx);
        sum += e.x + e.y + e.z + e.w;
        *(float4*)&sS[n][m0] = e;
    }
    float inv = 1.f / sum;

    float oacc[HDIM];
#pragma unroll
    for (int d = 0; d < HDIM; ++d) oacc[d] = 0.f;
#pragma unroll 2
    for (int m0 = 0; m0 < NTOK; m0 += 4) {
        float4 p4 = *(float4*)&sS[n][m0];
        float pw[4] = {p4.x * inv, p4.y * inv, p4.z * inv, p4.w * inv};
#pragma unroll
        for (int j = 0; j < 4; ++j) {
            int m = m0 + j;
#pragma unroll
            for (int d = 0; d < HDIM; d += 4) {
                float4 vv = *(const float4*)&sv[m][d];
                oacc[d]     += pw[j] * vv.x;
                oacc[d + 1] += pw[j] * vv.y;
                oacc[d + 2] += pw[j] * vv.z;
                oacc[d + 3] += pw[j] * vv.w;
            }
        }
    }

    size_t obase = (size_t)(win * NTOK + n) * QKVC + h * HDIM;
#pragma unroll
    for (int d = 0; d < HDIM; d += 4) {
        *(float4*)(qkv + obase + d) = make_float4(oacc[d], oacc[d + 1], oacc[d + 2], oacc[d + 3]);
    }
}

// ---------------- launch ----------------
extern "C" void kernel_launch(void* const* d_in, const int* in_sizes, int n_in,
                              void* d_out, int out_size) {
    const float* x      = (const float*)d_in[0];
    const float* g1     = (const float*)d_in[1];
    const float* be1    = (const float*)d_in[2];
    const float* w_qkv  = (const float*)d_in[3];
    const float* b_qkv  = (const float*)d_in[4];
    const float* pm_w1  = (const float*)d_in[5];
    const float* pm_b1  = (const float*)d_in[6];
    const float* pm_w2  = (const float*)d_in[7];
    const float* pm_b2  = (const float*)d_in[8];
    const float* w_proj = (const float*)d_in[9];
    const float* b_proj = (const float*)d_in[10];
    const float* g2     = (const float*)d_in[11];
    const float* be2    = (const float*)d_in[12];
    const float* w_fc1  = (const float*)d_in[13];
    const float* b_fc1  = (const float*)d_in[14];
    const float* w_fc2  = (const float*)d_in[15];
    const float* b_fc2  = (const float*)d_in[16];
    float* out = (float*)d_out;

    float *p_xw, *p_qkv, *p_x1, *p_hidden;
    cudaGetSymbolAddress((void**)&p_xw, g_xw);
    cudaGetSymbolAddress((void**)&p_qkv, g_qkv);
    cudaGetSymbolAddress((void**)&p_x1, g_x1);
    cudaGetSymbolAddress((void**)&p_hidden, g_hidden);

    cudaFuncSetAttribute(tgemm<0>, cudaFuncAttributeMaxDynamicSharedMemorySize, TG_SMEM);
    cudaFuncSetAttribute(tgemm<1>, cudaFuncAttributeMaxDynamicSharedMemorySize, TG_SMEM);
    cudaFuncSetAttribute(tgemm<2>, cudaFuncAttributeMaxDynamicSharedMemorySize, TG_SMEM);
    cudaFuncSetAttribute(tgemm<3>, cudaFuncAttributeMaxDynamicSharedMemorySize, TG_SMEM);

    // 1. positional bias table
    posbias_kernel<<<NTOK, NTOK>>>(pm_w1, pm_b1, pm_w2, pm_b2);

    // 2. LN1 + shifted-window gather -> g_xw
    ln_kernel<<<MROWS / 8, 256>>>(x, g1, be1, p_xw, 1);

    // 3. QKV GEMM
    tgemm<0><<<dim3(QKVC / 128, MROWS / 128), 256, TG_SMEM>>>(
        p_xw, CDIM, w_qkv, CDIM, b_qkv, p_qkv, QKVC, CDIM, nullptr);

    // 4. windowed attention (writes into q-region of g_qkv)
    attn_kernel<<<dim3(NWTOT, NH), 64>>>(p_qkv);

    // 5. proj GEMM + window-reverse scatter + residual -> g_x1
    tgemm<1><<<dim3(CDIM / 128, MROWS / 128), 256, TG_SMEM>>>(
        p_qkv, QKVC, w_proj, CDIM, b_proj, p_x1, CDIM, CDIM, x);

    // 6. LN2 -> g_xw
    ln_kernel<<<MROWS / 8, 256>>>(p_x1, g2, be2, p_xw, 0);

    // 7. FC1 + GELU -> g_hidden
    tgemm<2><<<dim3(HID / 128, MROWS / 128), 256, TG_SMEM>>>(
        p_xw, CDIM, w_fc1, CDIM, b_fc1, p_hidden, HID, CDIM, nullptr);

    // 8. FC2 + residual -> d_out
    tgemm<3><<<dim3(CDIM / 128, MROWS / 128), 256, TG_SMEM>>>(
        p_hidden, HID, w_fc2, HID, b_fc2, out, CDIM, HID, p_x1);
}

// round 5
// speedup vs baseline: 3.8200x; 1.2378x over previous
#include <cuda_runtime.h>
#include <math.h>
#include <cstdint>

// ---------------- problem constants ----------------
#define BB    32
#define HH    56
#define WWI   56
#define LTOK  3136          // 56*56
#define CDIM  512
#define NH    16
#define HDIM  32
#define WSZ   8
#define NTOK  64            // 8*8
#define SHFT  4
#define NWH   7
#define NWIN  49            // 7*7
#define NWTOT 1568          // BB*NWIN
#define MROWS 100352        // BB*LTOK = NWTOT*NTOK
#define HID   2048
#define QKVC  1536

// ---------------- static device scratch ----------------
__device__ float g_xw[(size_t)MROWS * CDIM];
__device__ float g_qkv[(size_t)MROWS * QKVC];
__device__ float g_x1[(size_t)MROWS * CDIM];
__device__ float g_hidden[(size_t)MROWS * HID];
__device__ float g_posbias[NH * NTOK * NTOK];

// ---------------- helpers ----------------
__device__ __forceinline__ uint32_t smem_u32(const void* p) {
    uint32_t a;
    asm("{ .reg .u64 t; cvta.to.shared.u64 t, %1; cvt.u32.u64 %0, t; }" : "=r"(a) : "l"(p));
    return a;
}
#define CP_ASYNC16(dst, src) \
    asm volatile("cp.async.cg.shared.global [%0], [%1], 16;" :: "r"(dst), "l"(src))
#define CP_COMMIT() asm volatile("cp.async.commit_group;" ::: "memory")
#define CP_WAIT(n)  asm volatile("cp.async.wait_group %0;" :: "n"(n) : "memory")

#define LDSM4(r, addr) \
    asm volatile("ldmatrix.sync.aligned.m8n8.x4.shared.b16 {%0,%1,%2,%3}, [%4];" \
        : "=r"((r)[0]), "=r"((r)[1]), "=r"((r)[2]), "=r"((r)[3]) : "r"(addr))

__device__ __forceinline__ void mma_tf32(float* d, const uint32_t* a, uint32_t b0, uint32_t b1) {
    asm volatile(
        "mma.sync.aligned.m16n8k8.row.col.f32.tf32.tf32.f32 "
        "{%0,%1,%2,%3}, {%4,%5,%6,%7}, {%8,%9}, {%0,%1,%2,%3};"
        : "+f"(d[0]), "+f"(d[1]), "+f"(d[2]), "+f"(d[3])
        : "r"(a[0]), "r"(a[1]), "r"(a[2]), "r"(a[3]), "r"(b0), "r"(b1));
}

// windowed row p -> flat row in original (B, H*W) layout
__device__ __forceinline__ size_t win_row_to_flat(int p) {
    int b   = p / LTOK;
    int rem = p - b * LTOK;
    int wl  = rem >> 6;
    int t   = rem & 63;
    int wh  = wl / NWH;
    int ww  = wl - wh * NWH;
    int r   = (wh * WSZ + (t >> 3) + SHFT) % HH;
    int c   = (ww * WSZ + (t & 7)  + SHFT) % WWI;
    return (size_t)b * LTOK + (size_t)r * WWI + c;
}

// ---------------- positional bias table ----------------
__global__ void posbias_kernel(const float* __restrict__ w1, const float* __restrict__ b1,
                               const float* __restrict__ w2, const float* __restrict__ b2) {
    int n = blockIdx.x;
    int m = threadIdx.x;
    float dh = (float)((n >> 3) - (m >> 3));
    float dw = (float)((n & 7)  - (m & 7));
    float fh = (dh > 0.f) ? log1pf(dh) : ((dh < 0.f) ? -log1pf(-dh) : 0.f);
    float fw = (dw > 0.f) ? log1pf(dw) : ((dw < 0.f) ? -log1pf(-dw) : 0.f);
    float hv[32];
#pragma unroll
    for (int o = 0; o < 32; ++o)
        hv[o] = fmaxf(w1[2 * o] * fh + w1[2 * o + 1] * fw + b1[o], 0.f);
#pragma unroll
    for (int hd = 0; hd < NH; ++hd) {
        float acc = b2[hd];
#pragma unroll
        for (int o = 0; o < 32; ++o) acc += w2[hd * 32 + o] * hv[o];
        g_posbias[hd * (NTOK * NTOK) + n * NTOK + m] = acc;
    }
}

// ---------------- LayerNorm: warp-per-row, 8 rows per 256-thread block ----------------
__global__ __launch_bounds__(256)
void ln_kernel(const float* __restrict__ in, const float* __restrict__ gamma,
               const float* __restrict__ beta, float* __restrict__ out, int gather) {
    int warp = threadIdx.x >> 5, lane = threadIdx.x & 31;
    int p = blockIdx.x * 8 + warp;
    size_t srow = gather ? win_row_to_flat(p) : (size_t)p;
    const float4* src = (const float4*)(in + srow * CDIM);
    float4 v[4];
#pragma unroll
    for (int i = 0; i < 4; ++i) v[i] = src[lane + 32 * i];
    float s = 0.f, q = 0.f;
#pragma unroll
    for (int i = 0; i < 4; ++i) {
        s += v[i].x + v[i].y + v[i].z + v[i].w;
        q += v[i].x * v[i].x + v[i].y * v[i].y + v[i].z * v[i].z + v[i].w * v[i].w;
    }
#pragma unroll
    for (int off = 16; off > 0; off >>= 1) {
        s += __shfl_xor_sync(0xFFFFFFFFu, s, off);
        q += __shfl_xor_sync(0xFFFFFFFFu, q, off);
    }
    float mean = s * (1.f / CDIM);
    float var  = q * (1.f / CDIM) - mean * mean;
    float rstd = rsqrtf(var + 1e-5f);
    float4* dst = (float4*)(out + (size_t)p * CDIM);
#pragma unroll
    for (int i = 0; i < 4; ++i) {
        float4 gg = ((const float4*)gamma)[lane + 32 * i];
        float4 bb = ((const float4*)beta)[lane + 32 * i];
        float4 o;
        o.x = (v[i].x - mean) * rstd * gg.x + bb.x;
        o.y = (v[i].y - mean) * rstd * gg.y + bb.y;
        o.z = (v[i].z - mean) * rstd * gg.z + bb.z;
        o.w = (v[i].w - mean) * rstd * gg.w + bb.w;
        dst[lane + 32 * i] = o;
    }
}

// ---------------- tf32 mma.sync GEMM NT, warp tile 64x64, 4 warps/CTA ----------------
// 128x128x16 CTA tile, 128 threads (4 warps, 2m x 2n), warp tile 64x64 (4x8 m16n8k8).
// MODE 0: C = acc + bias ; MODE 1: window-reverse scatter + residual
// MODE 2: gelu(acc+bias) ; MODE 3: res + acc + bias
#define BK 16
#define SSTR 20                      // smem row stride (floats)
#define STAGE_F (2 * 128 * SSTR)     // floats per stage (A tile + B tile)
#define NSTAGE 3
#define TG_SMEM (NSTAGE * STAGE_F * 4)

template<int MODE>
__global__ __launch_bounds__(128, 2)
void tgemm(const float* __restrict__ A, int lda,
           const float* __restrict__ B, int ldb,
           const float* __restrict__ bias,
           float* __restrict__ C, int ldc, int K,
           const float* __restrict__ res) {
    extern __shared__ float smf[];
    uint32_t sb = smem_u32(smf);

    int tid = threadIdx.x;
    int wid = tid >> 5, lane = tid & 31;
    int g   = lane >> 2;
    int tig = lane & 3;
    int warp_row = wid >> 1;      // 0..1 -> 64 rows
    int warp_col = wid & 1;       // 0..1 -> 64 cols

    const float* Ag = A + (size_t)(blockIdx.y * 128) * lda;
    const float* Bg = B + (size_t)(blockIdx.x * 128) * ldb;

    // cp.async task mapping: A tile has 512 16B-chunks, B tile has 512; 4 each per thread
    int r_t[4], cg_t[4];
#pragma unroll
    for (int i = 0; i < 4; ++i) {
        int task = i * 128 + tid;
        r_t[i]  = task >> 2;
        cg_t[i] = (task & 3) * 4;
    }

    // ldmatrix per-thread float offsets (within stage)
    uint32_t aoff[4];
#pragma unroll
    for (int mt = 0; mt < 4; ++mt)
        aoff[mt] = (uint32_t)((warp_row * 64 + mt * 16 + (lane & 15)) * SSTR + (lane >> 4) * 4);
    uint32_t boff[4];
    {
        int row_b = (lane & 7) + ((lane >> 4) << 3);
        int col_b = ((lane >> 3) & 1) * 4;
#pragma unroll
        for (int p = 0; p < 4; ++p)
            boff[p] = (uint32_t)(128 * SSTR + (warp_col * 64 + p * 16 + row_b) * SSTR + col_b);
    }

    float acc[4][8][4];
#pragma unroll
    for (int mt = 0; mt < 4; ++mt)
#pragma unroll
        for (int nt = 0; nt < 8; ++nt)
#pragma unroll
            for (int j = 0; j < 4; ++j) acc[mt][nt][j] = 0.f;

    int ntiles = K / BK;

    // prologue: tiles 0,1 into stages 0,1
#pragma unroll
    for (int s = 0; s < 2; ++s) {
        int k0 = s * BK;
        uint32_t st = sb + s * (STAGE_F * 4);
#pragma unroll
        for (int i = 0; i < 4; ++i) {
            CP_ASYNC16(st + (r_t[i] * SSTR + cg_t[i]) * 4, Ag + (size_t)r_t[i] * lda + k0 + cg_t[i]);
            CP_ASYNC16(st + (128 * SSTR + r_t[i] * SSTR + cg_t[i]) * 4, Bg + (size_t)r_t[i] * ldb + k0 + cg_t[i]);
        }
        CP_COMMIT();
    }

    int stage = 0;
    for (int t = 0; t < ntiles; ++t) {
        CP_WAIT(1);
        __syncthreads();
        if (t + 2 < ntiles) {
            int k0 = (t + 2) * BK;
            int s2 = stage + 2; if (s2 >= NSTAGE) s2 -= NSTAGE;
            uint32_t st = sb + s2 * (STAGE_F * 4);
#pragma unroll
            for (int i = 0; i < 4; ++i) {
                CP_ASYNC16(st + (r_t[i] * SSTR + cg_t[i]) * 4, Ag + (size_t)r_t[i] * lda + k0 + cg_t[i]);
                CP_ASYNC16(st + (128 * SSTR + r_t[i] * SSTR + cg_t[i]) * 4, Bg + (size_t)r_t[i] * ldb + k0 + cg_t[i]);
            }
        }
        CP_COMMIT();

        uint32_t sbase = sb + stage * (STAGE_F * 4);
#pragma unroll
        for (int ks = 0; ks < 2; ++ks) {
            uint32_t kb = ks * 32;   // byte offset: 8 floats
            uint32_t af[4][4], bf[4][4];
#pragma unroll
            for (int mt = 0; mt < 4; ++mt) LDSM4(af[mt], sbase + aoff[mt] * 4 + kb);
#pragma unroll
            for (int p = 0; p < 4; ++p)    LDSM4(bf[p], sbase + boff[p] * 4 + kb);
#pragma unroll
            for (int mt = 0; mt < 4; ++mt)
#pragma unroll
                for (int p = 0; p < 4; ++p) {
                    mma_tf32(acc[mt][2 * p + 0], af[mt], bf[p][0], bf[p][1]);
                    mma_tf32(acc[mt][2 * p + 1], af[mt], bf[p][2], bf[p][3]);
                }
        }
        if (++stage >= NSTAGE) stage -= NSTAGE;
    }

    // ---------------- epilogue ----------------
    int gr_base = blockIdx.y * 128 + warp_row * 64;
    int gc_base = blockIdx.x * 128 + warp_col * 64;

    size_t crow[4][2];
#pragma unroll
    for (int mt = 0; mt < 4; ++mt)
#pragma unroll
        for (int hf = 0; hf < 2; ++hf) {
            int gr = gr_base + mt * 16 + g + hf * 8;
            crow[mt][hf] = (MODE == 1) ? win_row_to_flat(gr) * (size_t)ldc : (size_t)gr * ldc;
        }

#pragma unroll
    for (int nt = 0; nt < 8; ++nt) {
        int col = gc_base + nt * 8 + tig * 2;
        float2 bs = *(const float2*)&bias[col];
#pragma unroll
        for (int mt = 0; mt < 4; ++mt)
#pragma unroll
            for (int hf = 0; hf < 2; ++hf) {
                float v0 = acc[mt][nt][hf * 2 + 0] + bs.x;
                float v1 = acc[mt][nt][hf * 2 + 1] + bs.y;
                if (MODE == 2) {
                    v0 = 0.5f * v0 * (1.0f + erff(v0 * 0.70710678118654752f));
                    v1 = 0.5f * v1 * (1.0f + erff(v1 * 0.70710678118654752f));
                }
                if (MODE == 1 || MODE == 3) {
                    float2 rr = *(const float2*)&res[crow[mt][hf] + col];
                    v0 += rr.x; v1 += rr.y;
                }
                *(float2*)&C[crow[mt][hf] + col] = make_float2(v0, v1);
            }
    }
}

// ---------------- windowed attention: one block per (window, head), 64 threads ----------------
__global__ __launch_bounds__(64)
void attn_kernel(float* __restrict__ qkv) {
    __shared__ float sq[NTOK][36];
    __shared__ float sk[NTOK][36];
    __shared__ float sv[NTOK][36];
    __shared__ float sS[NTOK][68];
    __shared__ int   sgb[NTOK];

    int win = blockIdx.x;
    int h   = blockIdx.y;
    int tid = threadIdx.x;
    int wl  = win % NWIN;
    int wh  = wl / NWH;
    int ww  = wl - wh * NWH;

    const float scale = 0.17677669529663687f;

    for (int i = tid; i < NTOK * 8; i += 64) {
        int row = i >> 3;
        int c4  = (i & 7) << 2;
        size_t base = (size_t)(win * NTOK + row) * QKVC + h * HDIM + c4;
        float4 qv = *(const float4*)(qkv + base);
        float4 kv = *(const float4*)(qkv + base + CDIM);
        float4 vv = *(const float4*)(qkv + base + 2 * CDIM);
        sq[row][c4 + 0] = qv.x * scale; sq[row][c4 + 1] = qv.y * scale;
        sq[row][c4 + 2] = qv.z * scale; sq[row][c4 + 3] = qv.w * scale;
        sk[row][c4 + 0] = kv.x; sk[row][c4 + 1] = kv.y;
        sk[row][c4 + 2] = kv.z; sk[row][c4 + 3] = kv.w;
        sv[row][c4 + 0] = vv.x; sv[row][c4 + 1] = vv.y;
        sv[row][c4 + 2] = vv.z; sv[row][c4 + 3] = vv.w;
    }
    {
        int t  = tid;
        int rr = wh * WSZ + (t >> 3);
        int cc = ww * WSZ + (t & 7);
        int gi = (rr < 48) ? 0 : ((rr < 52) ? 1 : 2);
        int gj = (cc < 48) ? 0 : ((cc < 52) ? 1 : 2);
        sgb[t] = gi * 3 + gj;
    }
    __syncthreads();

    int n = tid;
    float qr[HDIM];
#pragma unroll
    for (int d = 0; d < HDIM; d += 4) {
        float4 t4 = *(const float4*)&sq[n][d];
        qr[d] = t4.x; qr[d + 1] = t4.y; qr[d + 2] = t4.z; qr[d + 3] = t4.w;
    }

    const float* pb = g_posbias + h * (NTOK * NTOK) + n * NTOK;
    int gn = sgb[n];

    float mx = -1e30f;
#pragma unroll 2
    for (int m0 = 0; m0 < NTOK; m0 += 4) {
        float4 pbv = *(const float4*)&pb[m0];
        float a[4] = {pbv.x, pbv.y, pbv.z, pbv.w};
#pragma unroll
        for (int j = 0; j < 4; ++j) {
            int m = m0 + j;
            float s = 0.f;
#pragma unroll
            for (int d = 0; d < HDIM; d += 4) {
                float4 kv = *(const float4*)&sk[m][d];
                s += qr[d] * kv.x + qr[d + 1] * kv.y + qr[d + 2] * kv.z + qr[d + 3] * kv.w;
            }
            a[j] += s;
            if (gn != sgb[m]) a[j] -= 100.f;
            mx = fmaxf(mx, a[j]);
        }
        *(float4*)&sS[n][m0] = make_float4(a[0], a[1], a[2], a[3]);
    }

    float sum = 0.f;
#pragma unroll
    for (int m0 = 0; m0 < NTOK; m0 += 4) {
        float4 e = *(float4*)&sS[n][m0];
        e.x = __expf(e.x - mx); e.y = __expf(e.y - mx);
        e.z = __expf(e.z - mx); e.w = __expf(e.w - mx);
        sum += e.x + e.y + e.z + e.w;
        *(float4*)&sS[n][m0] = e;
    }
    float inv = 1.f / sum;

    float oacc[HDIM];
#pragma unroll
    for (int d = 0; d < HDIM; ++d) oacc[d] = 0.f;
#pragma unroll 2
    for (int m0 = 0; m0 < NTOK; m0 += 4) {
        float4 p4 = *(float4*)&sS[n][m0];
        float pw[4] = {p4.x * inv, p4.y * inv, p4.z * inv, p4.w * inv};
#pragma unroll
        for (int j = 0; j < 4; ++j) {
            int m = m0 + j;
#pragma unroll
            for (int d = 0; d < HDIM; d += 4) {
                float4 vv = *(const float4*)&sv[m][d];
                oacc[d]     += pw[j] * vv.x;
                oacc[d + 1] += pw[j] * vv.y;
                oacc[d + 2] += pw[j] * vv.z;
                oacc[d + 3] += pw[j] * vv.w;
            }
        }
    }

    size_t obase = (size_t)(win * NTOK + n) * QKVC + h * HDIM;
#pragma unroll
    for (int d = 0; d < HDIM; d += 4) {
        *(float4*)(qkv + obase + d) = make_float4(oacc[d], oacc[d + 1], oacc[d + 2], oacc[d + 3]);
    }
}

// ---------------- launch ----------------
extern "C" void kernel_launch(void* const* d_in, const int* in_sizes, int n_in,
                              void* d_out, int out_size) {
    const float* x      = (const float*)d_in[0];
    const float* g1     = (const float*)d_in[1];
    const float* be1    = (const float*)d_in[2];
    const float* w_qkv  = (const float*)d_in[3];
    const float* b_qkv  = (const float*)d_in[4];
    const float* pm_w1  = (const float*)d_in[5];
    const float* pm_b1  = (const float*)d_in[6];
    const float* pm_w2  = (const float*)d_in[7];
    const float* pm_b2  = (const float*)d_in[8];
    const float* w_proj = (const float*)d_in[9];
    const float* b_proj = (const float*)d_in[10];
    const float* g2     = (const float*)d_in[11];
    const float* be2    = (const float*)d_in[12];
    const float* w_fc1  = (const float*)d_in[13];
    const float* b_fc1  = (const float*)d_in[14];
    const float* w_fc2  = (const float*)d_in[15];
    const float* b_fc2  = (const float*)d_in[16];
    float* out = (float*)d_out;

    float *p_xw, *p_qkv, *p_x1, *p_hidden;
    cudaGetSymbolAddress((void**)&p_xw, g_xw);
    cudaGetSymbolAddress((void**)&p_qkv, g_qkv);
    cudaGetSymbolAddress((void**)&p_x1, g_x1);
    cudaGetSymbolAddress((void**)&p_hidden, g_hidden);

    cudaFuncSetAttribute(tgemm<0>, cudaFuncAttributeMaxDynamicSharedMemorySize, TG_SMEM);
    cudaFuncSetAttribute(tgemm<1>, cudaFuncAttributeMaxDynamicSharedMemorySize, TG_SMEM);
    cudaFuncSetAttribute(tgemm<2>, cudaFuncAttributeMaxDynamicSharedMemorySize, TG_SMEM);
    cudaFuncSetAttribute(tgemm<3>, cudaFuncAttributeMaxDynamicSharedMemorySize, TG_SMEM);

    // 1. positional bias table
    posbias_kernel<<<NTOK, NTOK>>>(pm_w1, pm_b1, pm_w2, pm_b2);

    // 2. LN1 + shifted-window gather -> g_xw
    ln_kernel<<<MROWS / 8, 256>>>(x, g1, be1, p_xw, 1);

    // 3. QKV GEMM
    tgemm<0><<<dim3(QKVC / 128, MROWS / 128), 128, TG_SMEM>>>(
        p_xw, CDIM, w_qkv, CDIM, b_qkv, p_qkv, QKVC, CDIM, nullptr);

    // 4. windowed attention (writes into q-region of g_qkv)
    attn_kernel<<<dim3(NWTOT, NH), 64>>>(p_qkv);

    // 5. proj GEMM + window-reverse scatter + residual -> g_x1
    tgemm<1><<<dim3(CDIM / 128, MROWS / 128), 128, TG_SMEM>>>(
        p_qkv, QKVC, w_proj, CDIM, b_proj, p_x1, CDIM, CDIM, x);

    // 6. LN2 -> g_xw
    ln_kernel<<<MROWS / 8, 256>>>(p_x1, g2, be2, p_xw, 0);

    // 7. FC1 + GELU -> g_hidden
    tgemm<2><<<dim3(HID / 128, MROWS / 128), 128, TG_SMEM>>>(
        p_xw, CDIM, w_fc1, CDIM, b_fc1, p_hidden, HID, CDIM, nullptr);

    // 8. FC2 + residual -> d_out
    tgemm<3><<<dim3(CDIM / 128, MROWS / 128), 128, TG_SMEM>>>(
        p_hidden, HID, w_fc2, HID, b_fc2, out, CDIM, HID, p_x1);
}

// round 6
// speedup vs baseline: 4.9906x; 1.3064x over previous
#include <cuda_runtime.h>
#include <cuda_fp16.h>
#include <math.h>
#include <cstdint>

// ---------------- problem constants ----------------
#define BB    32
#define HH    56
#define WWI   56
#define LTOK  3136          // 56*56
#define CDIM  512
#define NH    16
#define HDIM  32
#define WSZ   8
#define NTOK  64            // 8*8
#define SHFT  4
#define NWH   7
#define NWIN  49            // 7*7
#define NWTOT 1568          // BB*NWIN
#define MROWS 100352        // BB*LTOK = NWTOT*NTOK
#define HID   2048
#define QKVC  1536

// weight offsets in g_wh (halves)
#define WQ_OFF  0
#define WP_OFF  786432            // 1536*512
#define W1_OFF  1048576           // + 512*512
#define W2_OFF  2097152           // + 2048*512
#define WTOT    3145728           // + 512*2048

// ---------------- static device scratch ----------------
__device__ __half g_xw[(size_t)MROWS * CDIM];      // LN outputs (fp16)
__device__ __half g_qkv[(size_t)MROWS * QKVC];     // qkv fp16; q-region reused as attn out
__device__ float  g_x1[(size_t)MROWS * CDIM];      // residual after attention (fp32!)
__device__ __half g_hidden[(size_t)MROWS * HID];   // MLP hidden fp16
__device__ __half g_wh[WTOT];                      // fp16 weights
__device__ float  g_posbias[NH * NTOK * NTOK];

// ---------------- helpers ----------------
__device__ __forceinline__ uint32_t smem_u32(const void* p) {
    uint32_t a;
    asm("{ .reg .u64 t; cvta.to.shared.u64 t, %1; cvt.u32.u64 %0, t; }" : "=r"(a) : "l"(p));
    return a;
}
#define CP_ASYNC16(dst, src) \
    asm volatile("cp.async.cg.shared.global [%0], [%1], 16;" :: "r"(dst), "l"(src))
#define CP_COMMIT() asm volatile("cp.async.commit_group;" ::: "memory")
#define CP_WAIT(n)  asm volatile("cp.async.wait_group %0;" :: "n"(n) : "memory")

#define LDSM4(r, addr) \
    asm volatile("ldmatrix.sync.aligned.m8n8.x4.shared.b16 {%0,%1,%2,%3}, [%4];" \
        : "=r"((r)[0]), "=r"((r)[1]), "=r"((r)[2]), "=r"((r)[3]) : "r"(addr))

__device__ __forceinline__ void mma_f16(float* d, const uint32_t* a, uint32_t b0, uint32_t b1) {
    asm volatile(
        "mma.sync.aligned.m16n8k16.row.col.f32.f16.f16.f32 "
        "{%0,%1,%2,%3}, {%4,%5,%6,%7}, {%8,%9}, {%0,%1,%2,%3};"
        : "+f"(d[0]), "+f"(d[1]), "+f"(d[2]), "+f"(d[3])
        : "r"(a[0]), "r"(a[1]), "r"(a[2]), "r"(a[3]), "r"(b0), "r"(b1));
}

// windowed row p -> flat row in original (B, H*W) layout
__device__ __forceinline__ size_t win_row_to_flat(int p) {
    int b   = p / LTOK;
    int rem = p - b * LTOK;
    int wl  = rem >> 6;
    int t   = rem & 63;
    int wh  = wl / NWH;
    int ww  = wl - wh * NWH;
    int r   = (wh * WSZ + (t >> 3) + SHFT) % HH;
    int c   = (ww * WSZ + (t & 7)  + SHFT) % WWI;
    return (size_t)b * LTOK + (size_t)r * WWI + c;
}

// ---------------- weight fp32 -> fp16 conversion (4 elements/thread) ----------------
__global__ __launch_bounds__(256)
void cvtw_kernel(const float* __restrict__ wq, const float* __restrict__ wp,
                 const float* __restrict__ w1, const float* __restrict__ w2) {
    int i4 = (blockIdx.x * 256 + threadIdx.x) * 4;
    const float* src;
    int off;
    if      (i4 < WP_OFF) { src = wq; off = i4; }
    else if (i4 < W1_OFF) { src = wp; off = i4 - WP_OFF; }
    else if (i4 < W2_OFF) { src = w1; off = i4 - W1_OFF; }
    else                  { src = w2; off = i4 - W2_OFF; }
    float4 v = *(const float4*)(src + off);
    __half2 a = __floats2half2_rn(v.x, v.y);
    __half2 b = __floats2half2_rn(v.z, v.w);
    uint2 u;
    u.x = *(uint32_t*)&a;
    u.y = *(uint32_t*)&b;
    *(uint2*)&g_wh[i4] = u;
}

// ---------------- positional bias table ----------------
__global__ void posbias_kernel(const float* __restrict__ w1, const float* __restrict__ b1,
                               const float* __restrict__ w2, const float* __restrict__ b2) {
    int n = blockIdx.x;
    int m = threadIdx.x;
    float dh = (float)((n >> 3) - (m >> 3));
    float dw = (float)((n & 7)  - (m & 7));
    float fh = (dh > 0.f) ? log1pf(dh) : ((dh < 0.f) ? -log1pf(-dh) : 0.f);
    float fw = (dw > 0.f) ? log1pf(dw) : ((dw < 0.f) ? -log1pf(-dw) : 0.f);
    float hv[32];
#pragma unroll
    for (int o = 0; o < 32; ++o)
        hv[o] = fmaxf(w1[2 * o] * fh + w1[2 * o + 1] * fw + b1[o], 0.f);
#pragma unroll
    for (int hd = 0; hd < NH; ++hd) {
        float acc = b2[hd];
#pragma unroll
        for (int o = 0; o < 32; ++o) acc += w2[hd * 32 + o] * hv[o];
        g_posbias[hd * (NTOK * NTOK) + n * NTOK + m] = acc;
    }
}

// ---------------- LayerNorm: warp-per-row, fp32 in, fp16 out ----------------
__global__ __launch_bounds__(256)
void ln_kernel(const float* __restrict__ in, const float* __restrict__ gamma,
               const float* __restrict__ beta, __half* __restrict__ out, int gather) {
    int warp = threadIdx.x >> 5, lane = threadIdx.x & 31;
    int p = blockIdx.x * 8 + warp;
    size_t srow = gather ? win_row_to_flat(p) : (size_t)p;
    const float4* src = (const float4*)(in + srow * CDIM);
    float4 v[4];
#pragma unroll
    for (int i = 0; i < 4; ++i) v[i] = src[lane + 32 * i];
    float s = 0.f, q = 0.f;
#pragma unroll
    for (int i = 0; i < 4; ++i) {
        s += v[i].x + v[i].y + v[i].z + v[i].w;
        q += v[i].x * v[i].x + v[i].y * v[i].y + v[i].z * v[i].z + v[i].w * v[i].w;
    }
#pragma unroll
    for (int off = 16; off > 0; off >>= 1) {
        s += __shfl_xor_sync(0xFFFFFFFFu, s, off);
        q += __shfl_xor_sync(0xFFFFFFFFu, q, off);
    }
    float mean = s * (1.f / CDIM);
    float var  = q * (1.f / CDIM) - mean * mean;
    float rstd = rsqrtf(var + 1e-5f);
    uint2* dst = (uint2*)(out + (size_t)p * CDIM);
#pragma unroll
    for (int i = 0; i < 4; ++i) {
        int idx = lane + 32 * i;
        float4 gg = ((const float4*)gamma)[idx];
        float4 bb = ((const float4*)beta)[idx];
        float ox = (v[i].x - mean) * rstd * gg.x + bb.x;
        float oy = (v[i].y - mean) * rstd * gg.y + bb.y;
        float oz = (v[i].z - mean) * rstd * gg.z + bb.z;
        float ow = (v[i].w - mean) * rstd * gg.w + bb.w;
        __half2 h0 = __floats2half2_rn(ox, oy);
        __half2 h1 = __floats2half2_rn(oz, ow);
        uint2 u;
        u.x = *(uint32_t*)&h0;
        u.y = *(uint32_t*)&h1;
        dst[idx] = u;
    }
}

// ---------------- fp16 mma GEMM NT: C[M,N] = A[M,K]*B[N,K]^T + epilogue ----------------
// 128x128x32 CTA tile (BK=32 halves), 128 threads (4 warps 2x2), warp tile 64x64.
// MODE 0: C(half) = acc + bias ; MODE 1: C(float) scatter + residual
// MODE 2: C(half) = gelu(acc+bias) ; MODE 3: C(float) = res + acc + bias
#define BKH 32
#define SSTRH 40                       // smem row stride in halves
#define STAGE_H (2 * 128 * SSTRH)      // halves per stage
#define NSTAGE 3
#define TG_SMEM (NSTAGE * STAGE_H * 2)

template<int MODE>
__global__ __launch_bounds__(128, 2)
void tgemm(const __half* __restrict__ A, int lda,
           const __half* __restrict__ B, int ldb,
           const float* __restrict__ bias,
           void* __restrict__ Cv, int ldc, int K,
           const float* __restrict__ res) {
    extern __shared__ __half smh[];
    uint32_t sb = smem_u32(smh);

    int tid = threadIdx.x;
    int wid = tid >> 5, lane = tid & 31;
    int g   = lane >> 2;
    int tig = lane & 3;
    int warp_row = wid >> 1;
    int warp_col = wid & 1;

    const __half* Ag = A + (size_t)(blockIdx.y * 128) * lda;
    const __half* Bg = B + (size_t)(blockIdx.x * 128) * ldb;

    // cp.async tasks: per tile 512 chunks of 16B (128 rows x 4); 4 per thread per tensor
    int r_t[4], c_t[4];
#pragma unroll
    for (int i = 0; i < 4; ++i) {
        int task = i * 128 + tid;
        r_t[i] = task >> 2;
        c_t[i] = (task & 3);
    }

    // ldmatrix byte offsets within stage
    uint32_t aoff[4], boff[4];
#pragma unroll
    for (int mt = 0; mt < 4; ++mt)
        aoff[mt] = (uint32_t)(((warp_row * 64 + mt * 16 + (lane & 15)) * SSTRH) * 2 + (lane >> 4) * 16);
#pragma unroll
    for (int p = 0; p < 4; ++p)
        boff[p] = (uint32_t)((128 * SSTRH + (warp_col * 64 + p * 16 + (lane & 15)) * SSTRH) * 2 + (lane >> 4) * 16);

    float acc[4][8][4];
#pragma unroll
    for (int mt = 0; mt < 4; ++mt)
#pragma unroll
        for (int nt = 0; nt < 8; ++nt)
#pragma unroll
            for (int j = 0; j < 4; ++j) acc[mt][nt][j] = 0.f;

    int ntiles = K / BKH;

    // prologue: tiles 0,1 -> stages 0,1
#pragma unroll
    for (int s = 0; s < 2; ++s) {
        int k0 = s * BKH;
        uint32_t st = sb + s * (STAGE_H * 2);
#pragma unroll
        for (int i = 0; i < 4; ++i) {
            CP_ASYNC16(st + (r_t[i] * SSTRH) * 2 + c_t[i] * 16,
                       Ag + (size_t)r_t[i] * lda + k0 + c_t[i] * 8);
            CP_ASYNC16(st + (128 * SSTRH + r_t[i] * SSTRH) * 2 + c_t[i] * 16,
                       Bg + (size_t)r_t[i] * ldb + k0 + c_t[i] * 8);
        }
        CP_COMMIT();
    }

    int stage = 0;
    for (int t = 0; t < ntiles; ++t) {
        CP_WAIT(1);
        __syncthreads();
        if (t + 2 < ntiles) {
            int k0 = (t + 2) * BKH;
            int s2 = stage + 2; if (s2 >= NSTAGE) s2 -= NSTAGE;
            uint32_t st = sb + s2 * (STAGE_H * 2);
#pragma unroll
            for (int i = 0; i < 4; ++i) {
                CP_ASYNC16(st + (r_t[i] * SSTRH) * 2 + c_t[i] * 16,
                           Ag + (size_t)r_t[i] * lda + k0 + c_t[i] * 8);
                CP_ASYNC16(st + (128 * SSTRH + r_t[i] * SSTRH) * 2 + c_t[i] * 16,
                           Bg + (size_t)r_t[i] * ldb + k0 + c_t[i] * 8);
            }
        }
        CP_COMMIT();

        uint32_t sbase = sb + stage * (STAGE_H * 2);
#pragma unroll
        for (int ks = 0; ks < 2; ++ks) {
            uint32_t kb = ks * 32;       // 16 halves = 32 bytes
            uint32_t af[4][4], bf[4][4];
#pragma unroll
            for (int mt = 0; mt < 4; ++mt) LDSM4(af[mt], sbase + aoff[mt] + kb);
#pragma unroll
            for (int p = 0; p < 4; ++p)    LDSM4(bf[p], sbase + boff[p] + kb);
#pragma unroll
            for (int mt = 0; mt < 4; ++mt)
#pragma unroll
                for (int p = 0; p < 4; ++p) {
                    mma_f16(acc[mt][2 * p + 0], af[mt], bf[p][0], bf[p][2]);
                    mma_f16(acc[mt][2 * p + 1], af[mt], bf[p][1], bf[p][3]);
                }
        }
        if (++stage >= NSTAGE) stage -= NSTAGE;
    }

    // ---------------- epilogue ----------------
    int gr_base = blockIdx.y * 128 + warp_row * 64;
    int gc_base = blockIdx.x * 128 + warp_col * 64;

    size_t crow[4][2];
#pragma unroll
    for (int mt = 0; mt < 4; ++mt)
#pragma unroll
        for (int hf = 0; hf < 2; ++hf) {
            int gr = gr_base + mt * 16 + g + hf * 8;
            crow[mt][hf] = (MODE == 1) ? win_row_to_flat(gr) * (size_t)ldc : (size_t)gr * ldc;
        }

    __half* Ch = (__half*)Cv;
    float*  Cf = (float*)Cv;

#pragma unroll
    for (int nt = 0; nt < 8; ++nt) {
        int col = gc_base + nt * 8 + tig * 2;
        float2 bs = *(const float2*)&bias[col];
#pragma unroll
        for (int mt = 0; mt < 4; ++mt)
#pragma unroll
            for (int hf = 0; hf < 2; ++hf) {
                float v0 = acc[mt][nt][hf * 2 + 0] + bs.x;
                float v1 = acc[mt][nt][hf * 2 + 1] + bs.y;
                if (MODE == 2) {
                    v0 = 0.5f * v0 * (1.0f + erff(v0 * 0.70710678118654752f));
                    v1 = 0.5f * v1 * (1.0f + erff(v1 * 0.70710678118654752f));
                }
                if (MODE == 1 || MODE == 3) {
                    float2 rr = *(const float2*)&res[crow[mt][hf] + col];
                    v0 += rr.x; v1 += rr.y;
                    *(float2*)&Cf[crow[mt][hf] + col] = make_float2(v0, v1);
                } else {
                    __half2 hv = __floats2half2_rn(v0, v1);
                    *(__half2*)&Ch[crow[mt][hf] + col] = hv;
                }
            }
    }
}

// ---------------- windowed attention: half I/O, fp32 compute ----------------
__global__ __launch_bounds__(64)
void attn_kernel(__half* __restrict__ qkv) {
    __shared__ float sq[NTOK][36];
    __shared__ float sk[NTOK][36];
    __shared__ float sv[NTOK][36];
    __shared__ float sS[NTOK][68];
    __shared__ int   sgb[NTOK];

    int win = blockIdx.x;
    int h   = blockIdx.y;
    int tid = threadIdx.x;
    int wl  = win % NWIN;
    int wh  = wl / NWH;
    int ww  = wl - wh * NWH;

    const float scale = 0.17677669529663687f;

    // cooperative load: 64 rows x 32 halves per tensor; chunk = 8 halves
    for (int i = tid; i < NTOK * 4; i += 64) {
        int row = i >> 2;
        int c8  = (i & 3) * 8;
        size_t base = (size_t)(win * NTOK + row) * QKVC + h * HDIM + c8;
        uint4 qu = *(const uint4*)(qkv + base);
        uint4 ku = *(const uint4*)(qkv + base + CDIM);
        uint4 vu = *(const uint4*)(qkv + base + 2 * CDIM);
        const __half2* qh = (const __half2*)&qu;
        const __half2* kh = (const __half2*)&ku;
        const __half2* vh = (const __half2*)&vu;
#pragma unroll
        for (int j = 0; j < 4; ++j) {
            float2 qf = __half22float2(qh[j]);
            float2 kf = __half22float2(kh[j]);
            float2 vf = __half22float2(vh[j]);
            sq[row][c8 + 2 * j]     = qf.x * scale;
            sq[row][c8 + 2 * j + 1] = qf.y * scale;
            sk[row][c8 + 2 * j]     = kf.x;
            sk[row][c8 + 2 * j + 1] = kf.y;
            sv[row][c8 + 2 * j]     = vf.x;
            sv[row][c8 + 2 * j + 1] = vf.y;
        }
    }
    {
        int t  = tid;
        int rr = wh * WSZ + (t >> 3);
        int cc = ww * WSZ + (t & 7);
        int gi = (rr < 48) ? 0 : ((rr < 52) ? 1 : 2);
        int gj = (cc < 48) ? 0 : ((cc < 52) ? 1 : 2);
        sgb[t] = gi * 3 + gj;
    }
    __syncthreads();

    int n = tid;
    float qr[HDIM];
#pragma unroll
    for (int d = 0; d < HDIM; d += 4) {
        float4 t4 = *(const float4*)&sq[n][d];
        qr[d] = t4.x; qr[d + 1] = t4.y; qr[d + 2] = t4.z; qr[d + 3] = t4.w;
    }

    const float* pb = g_posbias + h * (NTOK * NTOK) + n * NTOK;
    int gn = sgb[n];

    float mx = -1e30f;
#pragma unroll 2
    for (int m0 = 0; m0 < NTOK; m0 += 4) {
        float4 pbv = *(const float4*)&pb[m0];
        float a[4] = {pbv.x, pbv.y, pbv.z, pbv.w};
#pragma unroll
        for (int j = 0; j < 4; ++j) {
            int m = m0 + j;
            float s = 0.f;
#pragma unroll
            for (int d = 0; d < HDIM; d += 4) {
                float4 kv = *(const float4*)&sk[m][d];
                s += qr[d] * kv.x + qr[d + 1] * kv.y + qr[d + 2] * kv.z + qr[d + 3] * kv.w;
            }
            a[j] += s;
            if (gn != sgb[m]) a[j] -= 100.f;
            mx = fmaxf(mx, a[j]);
        }
        *(float4*)&sS[n][m0] = make_float4(a[0], a[1], a[2], a[3]);
    }

    float sum = 0.f;
#pragma unroll
    for (int m0 = 0; m0 < NTOK; m0 += 4) {
        float4 e = *(float4*)&sS[n][m0];
        e.x = __expf(e.x - mx); e.y = __expf(e.y - mx);
        e.z = __expf(e.z - mx); e.w = __expf(e.w - mx);
        sum += e.x + e.y + e.z + e.w;
        *(float4*)&sS[n][m0] = e;
    }
    float inv = 1.f / sum;

    float oacc[HDIM];
#pragma unroll
    for (int d = 0; d < HDIM; ++d) oacc[d] = 0.f;
#pragma unroll 2
    for (int m0 = 0; m0 < NTOK; m0 += 4) {
        float4 p4 = *(float4*)&sS[n][m0];
        float pw[4] = {p4.x * inv, p4.y * inv, p4.z * inv, p4.w * inv};
#pragma unroll
        for (int j = 0; j < 4; ++j) {
            int m = m0 + j;
#pragma unroll
            for (int d = 0; d < HDIM; d += 4) {
                float4 vv = *(const float4*)&sv[m][d];
                oacc[d]     += pw[j] * vv.x;
                oacc[d + 1] += pw[j] * vv.y;
                oacc[d + 2] += pw[j] * vv.z;
                oacc[d + 3] += pw[j] * vv.w;
            }
        }
    }

    // write attn out (half) into q-region
    size_t obase = (size_t)(win * NTOK + n) * QKVC + h * HDIM;
#pragma unroll
    for (int d = 0; d < HDIM; d += 2) {
        __half2 hv = __floats2half2_rn(oacc[d], oacc[d + 1]);
        *(__half2*)(qkv + obase + d) = hv;
    }
}

// ---------------- launch ----------------
extern "C" void kernel_launch(void* const* d_in, const int* in_sizes, int n_in,
                              void* d_out, int out_size) {
    const float* x      = (const float*)d_in[0];
    const float* g1     = (const float*)d_in[1];
    const float* be1    = (const float*)d_in[2];
    const float* w_qkv  = (const float*)d_in[3];
    const float* b_qkv  = (const float*)d_in[4];
    const float* pm_w1  = (const float*)d_in[5];
    const float* pm_b1  = (const float*)d_in[6];
    const float* pm_w2  = (const float*)d_in[7];
    const float* pm_b2  = (const float*)d_in[8];
    const float* w_proj = (const float*)d_in[9];
    const float* b_proj = (const float*)d_in[10];
    const float* g2     = (const float*)d_in[11];
    const float* be2    = (const float*)d_in[12];
    const float* w_fc1  = (const float*)d_in[13];
    const float* b_fc1  = (const float*)d_in[14];
    const float* w_fc2  = (const float*)d_in[15];
    const float* b_fc2  = (const float*)d_in[16];
    float* out = (float*)d_out;

    __half *p_xw, *p_qkv, *p_hidden, *p_wh;
    float *p_x1;
    cudaGetSymbolAddress((void**)&p_xw, g_xw);
    cudaGetSymbolAddress((void**)&p_qkv, g_qkv);
    cudaGetSymbolAddress((void**)&p_x1, g_x1);
    cudaGetSymbolAddress((void**)&p_hidden, g_hidden);
    cudaGetSymbolAddress((void**)&p_wh, g_wh);

    cudaFuncSetAttribute(tgemm<0>, cudaFuncAttributeMaxDynamicSharedMemorySize, TG_SMEM);
    cudaFuncSetAttribute(tgemm<1>, cudaFuncAttributeMaxDynamicSharedMemorySize, TG_SMEM);
    cudaFuncSetAttribute(tgemm<2>, cudaFuncAttributeMaxDynamicSharedMemorySize, TG_SMEM);
    cudaFuncSetAttribute(tgemm<3>, cudaFuncAttributeMaxDynamicSharedMemorySize, TG_SMEM);

    // 0. weight conversion + positional bias
    cvtw_kernel<<<WTOT / 4 / 256, 256>>>(w_qkv, w_proj, w_fc1, w_fc2);
    posbias_kernel<<<NTOK, NTOK>>>(pm_w1, pm_b1, pm_w2, pm_b2);

    // 1. LN1 + shifted-window gather -> g_xw (fp16)
    ln_kernel<<<MROWS / 8, 256>>>(x, g1, be1, p_xw, 1);

    // 2. QKV GEMM (fp16 mma) -> g_qkv (fp16)
    tgemm<0><<<dim3(QKVC / 128, MROWS / 128), 128, TG_SMEM>>>(
        p_xw, CDIM, p_wh + WQ_OFF, CDIM, b_qkv, p_qkv, QKVC, CDIM, nullptr);

    // 3. windowed attention (half I/O, writes into q-region)
    attn_kernel<<<dim3(NWTOT, NH), 64>>>(p_qkv);

    // 4. proj GEMM + window-reverse scatter + residual -> g_x1 (fp32)
    tgemm<1><<<dim3(CDIM / 128, MROWS / 128), 128, TG_SMEM>>>(
        p_qkv, QKVC, p_wh + WP_OFF, CDIM, b_proj, p_x1, CDIM, CDIM, x);

    // 5. LN2 -> g_xw (fp16)
    ln_kernel<<<MROWS / 8, 256>>>(p_x1, g2, be2, p_xw, 0);

    // 6. FC1 + GELU -> g_hidden (fp16)
    tgemm<2><<<dim3(HID / 128, MROWS / 128), 128, TG_SMEM>>>(
        p_xw, CDIM, p_wh + W1_OFF, CDIM, b_fc1, p_hidden, HID, CDIM, nullptr);

    // 7. FC2 + residual -> d_out (fp32)
    tgemm<3><<<dim3(CDIM / 128, MROWS / 128), 128, TG_SMEM>>>(
        p_hidden, HID, p_wh + W2_OFF, HID, b_fc2, out, CDIM, HID, p_x1);
}